// round 1
// baseline (speedup 1.0000x reference)
#include <cuda_runtime.h>
#include <cuda_bf16.h>
#include <math.h>

// Problem constants
#define BATCH 16
#define C 256
#define HW 1024          // 32x32
#define HEADS 8
#define HDIM 32
#define M_TOTAL (BATCH * HW)   // 16384
#define KCONV (C * 9)          // 2304

// ---------------- scratch (static device globals; no runtime allocation) ---------
__device__ float g_w1t[KCONV * C];    // [K][N] bn1-folded conv1 weights
__device__ float g_w2t[KCONV * C];
__device__ float g_b1[C];
__device__ float g_b2[C];
__device__ float g_wqkv[C * 768];     // [K=256][N=768] (q|k|v transposed)
__device__ float g_bqkv[768];
__device__ float g_wot[C * C];        // out_w transposed
__device__ float g_t1[BATCH * C * HW];
__device__ float g_conv[BATCH * C * HW];
__device__ float g_qkv[BATCH * 768 * HW];
__device__ float g_attn[BATCH * C * HW];

// ---------------- weight transform + BN fold ----------------
__global__ void prep_kernel(
    const float* __restrict__ conv1_w, const float* __restrict__ conv1_b,
    const float* __restrict__ g1, const float* __restrict__ be1,
    const float* __restrict__ m1, const float* __restrict__ v1,
    const float* __restrict__ conv2_w, const float* __restrict__ conv2_b,
    const float* __restrict__ g2, const float* __restrict__ be2,
    const float* __restrict__ m2, const float* __restrict__ v2,
    const float* __restrict__ q_w, const float* __restrict__ q_b,
    const float* __restrict__ k_w, const float* __restrict__ k_b,
    const float* __restrict__ v_w, const float* __restrict__ v_b,
    const float* __restrict__ o_w)
{
    const int W1T_N = KCONV * C;          // 589824
    const int QKV_N = C * 768;            // 196608
    const int WOT_N = C * C;              // 65536
    const int total = 2 * W1T_N + QKV_N + WOT_N + 768 + 512;
    for (int i = blockIdx.x * blockDim.x + threadIdx.x; i < total;
         i += gridDim.x * blockDim.x) {
        if (i < W1T_N) {
            int k = i >> 8, o = i & 255;
            int c = k / 9, r = k - c * 9;
            float s = g1[o] * rsqrtf(v1[o] + 1e-5f);
            g_w1t[i] = conv1_w[(o * C + c) * 9 + r] * s;
        } else if (i < 2 * W1T_N) {
            int j = i - W1T_N;
            int k = j >> 8, o = j & 255;
            int c = k / 9, r = k - c * 9;
            float s = g2[o] * rsqrtf(v2[o] + 1e-5f);
            g_w2t[j] = conv2_w[(o * C + c) * 9 + r] * s;
        } else if (i < 2 * W1T_N + QKV_N) {
            int j = i - 2 * W1T_N;
            int c = j / 768, n = j - c * 768;
            float w;
            if (n < 256)      w = q_w[n * C + c];
            else if (n < 512) w = k_w[(n - 256) * C + c];
            else              w = v_w[(n - 512) * C + c];
            g_wqkv[j] = w;
        } else if (i < 2 * W1T_N + QKV_N + WOT_N) {
            int j = i - (2 * W1T_N + QKV_N);
            int c = j >> 8, o = j & 255;
            g_wot[j] = o_w[o * C + c];
        } else if (i < 2 * W1T_N + QKV_N + WOT_N + 768) {
            int n = i - (2 * W1T_N + QKV_N + WOT_N);
            float bb;
            if (n < 256)      bb = q_b[n];
            else if (n < 512) bb = k_b[n - 256];
            else              bb = v_b[n - 512];
            g_bqkv[n] = bb;
        } else {
            int j = i - (2 * W1T_N + QKV_N + WOT_N + 768); // 0..511
            int o = j & 255;
            if (j < 256) {
                float s = g1[o] * rsqrtf(v1[o] + 1e-5f);
                g_b1[o] = conv1_b[o] * s + be1[o] - m1[o] * s;
            } else {
                float s = g2[o] * rsqrtf(v2[o] + 1e-5f);
                g_b2[o] = conv2_b[o] * s + be2[o] - m2[o] * s;
            }
        }
    }
}

// ---------------- generic tiled GEMM (implicit-im2col capable) ----------------
// MODE 0: A is [B, Cin, HW], K = Cin (1x1 conv)
// MODE 1: A is [B, Cin, 32, 32], K = Cin*9 (3x3 conv, SAME padding)
// EPI 0: out = acc + bias
// EPI 1: out = relu(acc + bias)
// EPI 2: out = relu(conv + sigmoid(gate)*(acc + bias) + resid)
#define BM 128
#define BN 128
#define BKK 8

template<int MODE, int EPI>
__global__ void __launch_bounds__(256, 2) gemm_k(
    const float* __restrict__ A, const float* __restrict__ Bw,
    const float* __restrict__ bias, float* __restrict__ Cout,
    int Kdim, int Ndim,
    const float* __restrict__ convres, const float* __restrict__ resid,
    const float* __restrict__ gp)
{
    __shared__ float As[BKK][BM];
    __shared__ float Bs[BKK][BN];

    const int tid = threadIdx.x;
    const int m0 = blockIdx.x * BM;
    const int n0 = blockIdx.y * BN;

    const int ka = tid >> 5;          // 0..7
    const int ma = (tid & 31) * 4;    // 0..124
    const int ty = tid >> 4;          // 0..15
    const int tx = tid & 15;          // 0..15

    float acc[8][8];
#pragma unroll
    for (int i = 0; i < 8; i++)
#pragma unroll
        for (int j = 0; j < 8; j++) acc[i][j] = 0.f;

    for (int k0 = 0; k0 < Kdim; k0 += BKK) {
        const int kk = k0 + ka;
        // ---- load A tile
        if (MODE == 0) {
            int m = m0 + ma;
            int b = m >> 10, p = m & 1023;
            float4 av = *(const float4*)&A[((b * C + kk) << 10) + p];
            *(float4*)&As[ka][ma] = av;
        } else {
            int m = m0 + ma;
            int b = m >> 10, p = m & 1023;
            int y = p >> 5, xx = p & 31;
            int c = kk / 9, r = kk - c * 9;
            int dy = r / 3 - 1, dx = (r % 3) - 1;
            int yy = y + dy;
            const float* row = &A[((b * C + c) << 10) + yy * 32];
            float4 av;
            float* ap = (float*)&av;
#pragma unroll
            for (int t = 0; t < 4; t++) {
                int x2 = xx + t + dx;
                float v = 0.f;
                if ((unsigned)yy < 32u && (unsigned)x2 < 32u) v = row[x2];
                ap[t] = v;
            }
            *(float4*)&As[ka][ma] = av;
        }
        // ---- load B tile ([K][N] layout, coalesced)
        {
            float4 bv = *(const float4*)&Bw[(k0 + ka) * Ndim + n0 + ma];
            *(float4*)&Bs[ka][ma] = bv;
        }
        __syncthreads();
#pragma unroll
        for (int kk2 = 0; kk2 < BKK; kk2++) {
            float a[8], b[8];
            *(float4*)&a[0] = *(float4*)&As[kk2][ty * 4];
            *(float4*)&a[4] = *(float4*)&As[kk2][64 + ty * 4];
            *(float4*)&b[0] = *(float4*)&Bs[kk2][tx * 4];
            *(float4*)&b[4] = *(float4*)&Bs[kk2][64 + tx * 4];
#pragma unroll
            for (int i = 0; i < 8; i++)
#pragma unroll
                for (int j = 0; j < 8; j++)
                    acc[i][j] += a[i] * b[j];
        }
        __syncthreads();
    }

    // ---- epilogue
    float sg = 0.f;
    if (EPI == 2) sg = 1.f / (1.f + __expf(-gp[0]));
#pragma unroll
    for (int ih = 0; ih < 2; ih++) {
        int m = m0 + ih * 64 + ty * 4;
        int b = m >> 10, p = m & 1023;
#pragma unroll
        for (int jh = 0; jh < 2; jh++) {
#pragma unroll
            for (int j = 0; j < 4; j++) {
                int n = n0 + jh * 64 + tx * 4 + j;
                float bb = bias[n];
                int addr = ((b * Ndim + n) << 10) + p;
                float4 v;
                v.x = acc[ih * 4 + 0][jh * 4 + j] + bb;
                v.y = acc[ih * 4 + 1][jh * 4 + j] + bb;
                v.z = acc[ih * 4 + 2][jh * 4 + j] + bb;
                v.w = acc[ih * 4 + 3][jh * 4 + j] + bb;
                if (EPI == 1) {
                    v.x = fmaxf(v.x, 0.f); v.y = fmaxf(v.y, 0.f);
                    v.z = fmaxf(v.z, 0.f); v.w = fmaxf(v.w, 0.f);
                } else if (EPI == 2) {
                    float4 cv = *(const float4*)&convres[addr];
                    float4 rv = *(const float4*)&resid[addr];
                    v.x = fmaxf(cv.x + sg * v.x + rv.x, 0.f);
                    v.y = fmaxf(cv.y + sg * v.y + rv.y, 0.f);
                    v.z = fmaxf(cv.z + sg * v.z + rv.z, 0.f);
                    v.w = fmaxf(cv.w + sg * v.w + rv.w, 0.f);
                }
                *(float4*)&Cout[addr] = v;
            }
        }
    }
}

// ---------------- attention kernel ----------------
// one block per (b, h, 32-query tile). Full 32x1024 score tile in smem.
// smem layout (floats): sS[1024][34] | sQ[32*32] | sKV[32*64] | sInvZ[32]
#define SROW 34

__global__ void __launch_bounds__(256, 1) attn_kernel(
    const float* __restrict__ qkv, float* __restrict__ out)
{
    extern __shared__ float sm[];
    float* sS   = sm;                    // [m][n] : 1024 x 34
    float* sQ   = sS + 1024 * SROW;      // [d][n] : 32 x 32
    float* sKV  = sQ + 32 * 32;          // [d][mm]: 32 x 64
    float* sInv = sKV + 32 * 64;         // [32]

    const int tid = threadIdx.x;
    const int n0 = blockIdx.x * 32;
    const int h  = blockIdx.y;
    const int b  = blockIdx.z;

    const float* qbase = qkv + (b * 768 + h * HDIM) * HW;
    const float* kbase = qbase + 256 * HW;
    const float* vbase = qbase + 512 * HW;

    // load Q tile [32 d][32 n]
    for (int i = tid; i < 1024; i += 256) {
        int d = i >> 5, n = i & 31;
        sQ[d * 32 + n] = qbase[d * HW + n0 + n];
    }

    const int tyA = tid >> 4;   // 0..15 -> n pair
    const int txA = tid & 15;   // 0..15 -> 4 m's
    const float scale = 0.17677669529663687f;  // 1/sqrt(32)

    // ---- phase A: scores
    for (int mt = 0; mt < 16; mt++) {
        __syncthreads();
        for (int i = tid; i < 2048; i += 256) {
            int d = i >> 6, mm = i & 63;
            sKV[d * 64 + mm] = kbase[d * HW + mt * 64 + mm];
        }
        __syncthreads();
        float acc0[4] = {0.f, 0.f, 0.f, 0.f};
        float acc1[4] = {0.f, 0.f, 0.f, 0.f};
#pragma unroll
        for (int d = 0; d < 32; d++) {
            float a0 = sQ[d * 32 + tyA * 2];
            float a1 = sQ[d * 32 + tyA * 2 + 1];
            float4 bv = *(float4*)&sKV[d * 64 + txA * 4];
            acc0[0] += a0 * bv.x; acc0[1] += a0 * bv.y;
            acc0[2] += a0 * bv.z; acc0[3] += a0 * bv.w;
            acc1[0] += a1 * bv.x; acc1[1] += a1 * bv.y;
            acc1[2] += a1 * bv.z; acc1[3] += a1 * bv.w;
        }
#pragma unroll
        for (int q = 0; q < 4; q++) {
            int m = mt * 64 + txA * 4 + q;
            sS[m * SROW + tyA * 2]     = acc0[q] * scale;
            sS[m * SROW + tyA * 2 + 1] = acc1[q] * scale;
        }
    }
    __syncthreads();

    // ---- phase B: softmax over m (per query column n)
    {
        int w = tid >> 5, lane = tid & 31;
#pragma unroll
        for (int r = 0; r < 4; r++) {
            int n = w * 4 + r;
            float mx = -1e30f;
            for (int m = lane; m < 1024; m += 32)
                mx = fmaxf(mx, sS[m * SROW + n]);
#pragma unroll
            for (int off = 16; off; off >>= 1)
                mx = fmaxf(mx, __shfl_xor_sync(0xffffffffu, mx, off));
            float sum = 0.f;
            for (int m = lane; m < 1024; m += 32) {
                float e = __expf(sS[m * SROW + n] - mx);
                sS[m * SROW + n] = e;
                sum += e;
            }
#pragma unroll
            for (int off = 16; off; off >>= 1)
                sum += __shfl_xor_sync(0xffffffffu, sum, off);
            if (lane == 0) sInv[n] = 1.f / sum;
        }
    }

    // ---- phase C: O = V * A^T  (out[d][n] = sum_m v[d][m] * s[m][n])
    const int tyC = tid >> 4;   // d pair
    const int txC = tid & 15;   // n pair
    float o00 = 0.f, o01 = 0.f, o10 = 0.f, o11 = 0.f;
    for (int mt = 0; mt < 16; mt++) {
        __syncthreads();
        for (int i = tid; i < 2048; i += 256) {
            int d = i >> 6, mm = i & 63;
            sKV[d * 64 + mm] = vbase[d * HW + mt * 64 + mm];
        }
        __syncthreads();
#pragma unroll 8
        for (int mm = 0; mm < 64; mm++) {
            int m = mt * 64 + mm;
            float v0 = sKV[(tyC * 2) * 64 + mm];
            float v1 = sKV[(tyC * 2 + 1) * 64 + mm];
            float2 s = *(float2*)&sS[m * SROW + txC * 2];
            o00 += v0 * s.x; o01 += v0 * s.y;
            o10 += v1 * s.x; o11 += v1 * s.y;
        }
    }
    float iz0 = sInv[txC * 2], iz1 = sInv[txC * 2 + 1];
    int cb = (b * C + h * HDIM + tyC * 2) * HW + n0 + txC * 2;
    out[cb]          = o00 * iz0;
    out[cb + 1]      = o01 * iz1;
    out[cb + HW]     = o10 * iz0;
    out[cb + HW + 1] = o11 * iz1;
}

// ---------------- launch ----------------
extern "C" void kernel_launch(void* const* d_in, const int* in_sizes, int n_in,
                              void* d_out, int out_size)
{
    const float* x       = (const float*)d_in[0];
    const float* conv1_w = (const float*)d_in[1];
    const float* conv1_b = (const float*)d_in[2];
    const float* bn1_g   = (const float*)d_in[3];
    const float* bn1_b   = (const float*)d_in[4];
    const float* bn1_m   = (const float*)d_in[5];
    const float* bn1_v   = (const float*)d_in[6];
    const float* conv2_w = (const float*)d_in[7];
    const float* conv2_b = (const float*)d_in[8];
    const float* bn2_g   = (const float*)d_in[9];
    const float* bn2_b   = (const float*)d_in[10];
    const float* bn2_m   = (const float*)d_in[11];
    const float* bn2_v   = (const float*)d_in[12];
    const float* q_w     = (const float*)d_in[13];
    const float* q_b     = (const float*)d_in[14];
    const float* k_w     = (const float*)d_in[15];
    const float* k_b     = (const float*)d_in[16];
    const float* v_w     = (const float*)d_in[17];
    const float* v_b     = (const float*)d_in[18];
    const float* o_w     = (const float*)d_in[19];
    const float* o_b     = (const float*)d_in[20];
    const float* gate    = (const float*)d_in[21];
    float* out           = (float*)d_out;

    // resolve scratch symbol addresses (host query only; no allocation)
    float *p_w1t, *p_w2t, *p_b1, *p_b2, *p_wqkv, *p_bqkv, *p_wot;
    float *p_t1, *p_conv, *p_qkv, *p_attn;
    cudaGetSymbolAddress((void**)&p_w1t,  g_w1t);
    cudaGetSymbolAddress((void**)&p_w2t,  g_w2t);
    cudaGetSymbolAddress((void**)&p_b1,   g_b1);
    cudaGetSymbolAddress((void**)&p_b2,   g_b2);
    cudaGetSymbolAddress((void**)&p_wqkv, g_wqkv);
    cudaGetSymbolAddress((void**)&p_bqkv, g_bqkv);
    cudaGetSymbolAddress((void**)&p_wot,  g_wot);
    cudaGetSymbolAddress((void**)&p_t1,   g_t1);
    cudaGetSymbolAddress((void**)&p_conv, g_conv);
    cudaGetSymbolAddress((void**)&p_qkv,  g_qkv);
    cudaGetSymbolAddress((void**)&p_attn, g_attn);

    // weight transform + BN fold
    prep_kernel<<<2048, 256>>>(conv1_w, conv1_b, bn1_g, bn1_b, bn1_m, bn1_v,
                               conv2_w, conv2_b, bn2_g, bn2_b, bn2_m, bn2_v,
                               q_w, q_b, k_w, k_b, v_w, v_b, o_w);

    // conv1 (3x3) + BN + relu -> t1
    dim3 gConv(M_TOTAL / BM, C / BN);
    gemm_k<1, 1><<<gConv, 256>>>(x, p_w1t, p_b1, p_t1, KCONV, C,
                                 nullptr, nullptr, nullptr);
    // conv2 (3x3) + BN -> conv_out
    gemm_k<1, 0><<<gConv, 256>>>(p_t1, p_w2t, p_b2, p_conv, KCONV, C,
                                 nullptr, nullptr, nullptr);
    // fused qkv (1x1) -> qkv buffer
    dim3 gQKV(M_TOTAL / BM, 768 / BN);
    gemm_k<0, 0><<<gQKV, 256>>>(x, p_wqkv, p_bqkv, p_qkv, C, 768,
                                nullptr, nullptr, nullptr);

    // attention
    const int attn_smem = (1024 * SROW + 32 * 32 + 32 * 64 + 32) * (int)sizeof(float);
    cudaFuncSetAttribute(attn_kernel, cudaFuncAttributeMaxDynamicSharedMemorySize,
                         attn_smem);
    dim3 gAttn(HW / 32, HEADS, BATCH);
    attn_kernel<<<gAttn, 256, attn_smem>>>(p_qkv, p_attn);

    // out-proj (1x1) + gate + conv residual + input residual + relu -> out
    dim3 gOut(M_TOTAL / BM, C / BN);
    gemm_k<0, 2><<<gOut, 256>>>(p_attn, p_wot, o_b, out, C, C,
                                p_conv, x, gate);
}

// round 2
// speedup vs baseline: 1.7172x; 1.7172x over previous
#include <cuda_runtime.h>
#include <cuda_bf16.h>
#include <math.h>

// Problem constants
#define BATCH 16
#define C 256
#define HW 1024          // 32x32
#define HEADS 8
#define HDIM 32
#define M_TOTAL (BATCH * HW)   // 16384
#define KCONV (C * 9)          // 2304

// ---------------- scratch (static device globals; no runtime allocation) ---------
__device__ float g_w1t[KCONV * C];    // [K][N] bn1-folded conv1 weights
__device__ float g_w2t[KCONV * C];
__device__ float g_b1[C];
__device__ float g_b2[C];
__device__ float g_wqkv[C * 768];     // [K=256][N=768] (q|k|v transposed)
__device__ float g_bqkv[768];
__device__ float g_wot[C * C];        // out_w transposed
__device__ float g_t1[BATCH * C * HW];
__device__ float g_conv[BATCH * C * HW];
__device__ float g_qkv[BATCH * 768 * HW];
__device__ float g_attn[BATCH * C * HW];

// ---------------- tf32 helpers ----------------
__device__ __forceinline__ float to_tf32(float x) {
    float y;
    asm("cvt.rna.tf32.f32 %0, %1;" : "=f"(y) : "f"(x));
    return y;
}

__device__ __forceinline__ void mma_tf32(float* c, const unsigned* a, const unsigned* b) {
    asm volatile(
        "mma.sync.aligned.m16n8k8.row.col.f32.tf32.tf32.f32 "
        "{%0,%1,%2,%3}, {%4,%5,%6,%7}, {%8,%9}, {%0,%1,%2,%3};\n"
        : "+f"(c[0]), "+f"(c[1]), "+f"(c[2]), "+f"(c[3])
        : "r"(a[0]), "r"(a[1]), "r"(a[2]), "r"(a[3]), "r"(b[0]), "r"(b[1]));
}

// ---------------- weight transform + BN fold ----------------
__global__ void prep_kernel(
    const float* __restrict__ conv1_w, const float* __restrict__ conv1_b,
    const float* __restrict__ g1, const float* __restrict__ be1,
    const float* __restrict__ m1, const float* __restrict__ v1,
    const float* __restrict__ conv2_w, const float* __restrict__ conv2_b,
    const float* __restrict__ g2, const float* __restrict__ be2,
    const float* __restrict__ m2, const float* __restrict__ v2,
    const float* __restrict__ q_w, const float* __restrict__ q_b,
    const float* __restrict__ k_w, const float* __restrict__ k_b,
    const float* __restrict__ v_w, const float* __restrict__ v_b,
    const float* __restrict__ o_w)
{
    const int W1T_N = KCONV * C;          // 589824
    const int QKV_N = C * 768;            // 196608
    const int WOT_N = C * C;              // 65536
    const int total = 2 * W1T_N + QKV_N + WOT_N + 768 + 512;
    for (int i = blockIdx.x * blockDim.x + threadIdx.x; i < total;
         i += gridDim.x * blockDim.x) {
        if (i < W1T_N) {
            int k = i >> 8, o = i & 255;
            int c = k / 9, r = k - c * 9;
            float s = g1[o] * rsqrtf(v1[o] + 1e-5f);
            g_w1t[i] = conv1_w[(o * C + c) * 9 + r] * s;
        } else if (i < 2 * W1T_N) {
            int j = i - W1T_N;
            int k = j >> 8, o = j & 255;
            int c = k / 9, r = k - c * 9;
            float s = g2[o] * rsqrtf(v2[o] + 1e-5f);
            g_w2t[j] = conv2_w[(o * C + c) * 9 + r] * s;
        } else if (i < 2 * W1T_N + QKV_N) {
            int j = i - 2 * W1T_N;
            int c = j / 768, n = j - c * 768;
            float w;
            if (n < 256)      w = q_w[n * C + c];
            else if (n < 512) w = k_w[(n - 256) * C + c];
            else              w = v_w[(n - 512) * C + c];
            g_wqkv[j] = w;
        } else if (i < 2 * W1T_N + QKV_N + WOT_N) {
            int j = i - (2 * W1T_N + QKV_N);
            int c = j >> 8, o = j & 255;
            g_wot[j] = o_w[o * C + c];
        } else if (i < 2 * W1T_N + QKV_N + WOT_N + 768) {
            int n = i - (2 * W1T_N + QKV_N + WOT_N);
            float bb;
            if (n < 256)      bb = q_b[n];
            else if (n < 512) bb = k_b[n - 256];
            else              bb = v_b[n - 512];
            g_bqkv[n] = bb;
        } else {
            int j = i - (2 * W1T_N + QKV_N + WOT_N + 768); // 0..511
            int o = j & 255;
            if (j < 256) {
                float s = g1[o] * rsqrtf(v1[o] + 1e-5f);
                g_b1[o] = conv1_b[o] * s + be1[o] - m1[o] * s;
            } else {
                float s = g2[o] * rsqrtf(v2[o] + 1e-5f);
                g_b2[o] = conv2_b[o] * s + be2[o] - m2[o] * s;
            }
        }
    }
}

// ---------------- TF32 tensor-core GEMM (implicit-im2col capable) ----------------
// MODE 0: A is [B, Cin, HW], K = Cin (1x1 conv)
// MODE 1: A is [B, Cin, 32, 32], K = Cin*9 (3x3 conv, SAME padding)
// EPI 0: out = acc + bias
// EPI 1: out = relu(acc + bias)
// EPI 2: out = relu(conv + sigmoid(gate)*(acc + bias) + resid)
#define BM 128
#define BN 128
#define BKT 16
#define SAS 20   // smem row stride for [m][k] / [n][k]; 20 % 32 = 20 -> conflict-free frags

template<int MODE, int EPI>
__global__ void __launch_bounds__(256, 2) gemm_k(
    const float* __restrict__ A, const float* __restrict__ Bw,
    const float* __restrict__ bias, float* __restrict__ Cout,
    int Kdim, int Ndim,
    const float* __restrict__ convres, const float* __restrict__ resid,
    const float* __restrict__ gp)
{
    __shared__ float sA[BM * SAS];   // [m][k]
    __shared__ float sB[BN * SAS];   // [n][k]

    const int tid  = threadIdx.x;
    const int lane = tid & 31;
    const int wid  = tid >> 5;
    const int wm   = wid & 1;        // 0..1 -> m offset 64*wm
    const int wn   = wid >> 1;       // 0..3 -> n offset 32*wn
    const int m0 = blockIdx.x * BM;
    const int n0 = blockIdx.y * BN;
    const int bq = m0 >> 10;
    const int p0 = m0 & 1023;

    const int kk = tid & 15;          // k within tile
    const int cb = (tid >> 4) * 8;    // m / n chunk base

    float acc[4][4][4];
#pragma unroll
    for (int i = 0; i < 4; i++)
#pragma unroll
        for (int j = 0; j < 4; j++)
#pragma unroll
            for (int q = 0; q < 4; q++) acc[i][j][q] = 0.f;

    for (int k0 = 0; k0 < Kdim; k0 += BKT) {
        const int k = k0 + kk;
        // ---- stage A tile -> sA[m][k]
        if (MODE == 0) {
            const float* src = A + (((size_t)bq * C + k) << 10) + p0 + cb;
            float4 v0 = *(const float4*)(src);
            float4 v1 = *(const float4*)(src + 4);
            sA[(cb + 0) * SAS + kk] = to_tf32(v0.x);
            sA[(cb + 1) * SAS + kk] = to_tf32(v0.y);
            sA[(cb + 2) * SAS + kk] = to_tf32(v0.z);
            sA[(cb + 3) * SAS + kk] = to_tf32(v0.w);
            sA[(cb + 4) * SAS + kk] = to_tf32(v1.x);
            sA[(cb + 5) * SAS + kk] = to_tf32(v1.y);
            sA[(cb + 6) * SAS + kk] = to_tf32(v1.z);
            sA[(cb + 7) * SAS + kk] = to_tf32(v1.w);
        } else {
            int c = k / 9, r = k - c * 9;
            int dy = r / 3 - 1, dx = (r % 3) - 1;
            int p = p0 + cb;
            int y = (p >> 5) + dy;
            bool yok = ((unsigned)y < 32u);
            const float* row = A + (((size_t)bq * C + c) << 10) + (y << 5);
#pragma unroll
            for (int i = 0; i < 8; i++) {
                int x = ((p + i) & 31) + dx;
                float v = (yok && (unsigned)x < 32u) ? row[x] : 0.f;
                sA[(cb + i) * SAS + kk] = to_tf32(v);
            }
        }
        // ---- stage B tile -> sB[n][k]
        {
            const float* src = Bw + (size_t)k * Ndim + n0 + cb;
            float4 v0 = *(const float4*)(src);
            float4 v1 = *(const float4*)(src + 4);
            sB[(cb + 0) * SAS + kk] = to_tf32(v0.x);
            sB[(cb + 1) * SAS + kk] = to_tf32(v0.y);
            sB[(cb + 2) * SAS + kk] = to_tf32(v0.z);
            sB[(cb + 3) * SAS + kk] = to_tf32(v0.w);
            sB[(cb + 4) * SAS + kk] = to_tf32(v1.x);
            sB[(cb + 5) * SAS + kk] = to_tf32(v1.y);
            sB[(cb + 6) * SAS + kk] = to_tf32(v1.z);
            sB[(cb + 7) * SAS + kk] = to_tf32(v1.w);
        }
        __syncthreads();

#pragma unroll
        for (int ks = 0; ks < 2; ks++) {
            const int acol = ks * 8 + (lane & 3);
            unsigned af[4][4], bf[4][2];
#pragma unroll
            for (int mi = 0; mi < 4; mi++) {
                int ar = wm * 64 + mi * 16 + (lane >> 2);
                af[mi][0] = __float_as_uint(sA[ar * SAS + acol]);
                af[mi][1] = __float_as_uint(sA[(ar + 8) * SAS + acol]);
                af[mi][2] = __float_as_uint(sA[ar * SAS + acol + 4]);
                af[mi][3] = __float_as_uint(sA[(ar + 8) * SAS + acol + 4]);
            }
#pragma unroll
            for (int nj = 0; nj < 4; nj++) {
                int br = wn * 32 + nj * 8 + (lane >> 2);
                bf[nj][0] = __float_as_uint(sB[br * SAS + acol]);
                bf[nj][1] = __float_as_uint(sB[br * SAS + acol + 4]);
            }
#pragma unroll
            for (int mi = 0; mi < 4; mi++)
#pragma unroll
                for (int nj = 0; nj < 4; nj++)
                    mma_tf32(acc[mi][nj], af[mi], bf[nj]);
        }
        __syncthreads();
    }

    // ---- epilogue
    float sg = 0.f;
    if (EPI == 2) sg = 1.f / (1.f + __expf(-gp[0]));
#pragma unroll
    for (int mi = 0; mi < 4; mi++) {
#pragma unroll
        for (int half = 0; half < 2; half++) {
            int m = m0 + wm * 64 + mi * 16 + (lane >> 2) + half * 8;
            int mb = m >> 10, p = m & 1023;
#pragma unroll
            for (int nj = 0; nj < 4; nj++) {
                int n = n0 + wn * 32 + nj * 8 + 2 * (lane & 3);
                float v0 = acc[mi][nj][half * 2 + 0] + bias[n];
                float v1 = acc[mi][nj][half * 2 + 1] + bias[n + 1];
                size_t addr = (((size_t)mb * Ndim + n) << 10) + p;
                if (EPI == 1) {
                    v0 = fmaxf(v0, 0.f); v1 = fmaxf(v1, 0.f);
                } else if (EPI == 2) {
                    float c0 = convres[addr], c1 = convres[addr + 1024];
                    float r0 = resid[addr],   r1 = resid[addr + 1024];
                    v0 = fmaxf(c0 + sg * v0 + r0, 0.f);
                    v1 = fmaxf(c1 + sg * v1 + r1, 0.f);
                }
                Cout[addr]        = v0;
                Cout[addr + 1024] = v1;
            }
        }
    }
}

// ---------------- attention kernel (TF32 mma) ----------------
// one block per (b, h, 32-query tile). S tile [32 q][1024 k] in smem.
#define SSTR 1044   // 1044 % 32 = 20 -> conflict-free P-frag loads
#define QSTR 36     // sQ [q][d]
#define KSTR 33     // sK [key][d]
#define VSTR 132    // sV [d][key]

__global__ void __launch_bounds__(256, 1) attn_kernel(
    const float* __restrict__ qkv, float* __restrict__ out)
{
    extern __shared__ float sm[];
    float* sS   = sm;                    // [32][SSTR]
    float* sQ   = sS + 32 * SSTR;        // [32][QSTR]
    float* sK   = sQ + 32 * QSTR;        // [128][KSTR]
    float* sV   = sK + 128 * KSTR;       // [32][VSTR]
    float* sO   = sV + 32 * VSTR;        // [8][32][33]
    float* sInv = sO + 8 * 32 * 33;      // [32]

    const int tid  = threadIdx.x;
    const int lane = tid & 31;
    const int w    = tid >> 5;
    const int n0 = blockIdx.x * 32;
    const int h  = blockIdx.y;
    const int b  = blockIdx.z;

    const float* qbase = qkv + ((size_t)b * 768 + h * HDIM) * HW;
    const float* kbase = qbase + 256 * HW;
    const float* vbase = qbase + 512 * HW;
    const float scale = 0.17677669529663687f;  // 1/sqrt(32)

    // ---- stage Q (transpose to [q][d], tf32-rounded)
    for (int i = tid; i < 1024; i += 256) {
        int d = i >> 5, q = i & 31;
        sQ[q * QSTR + d] = to_tf32(qbase[d * HW + n0 + q]);
    }
    __syncthreads();

    // hoisted A-frags of Q: [mi][ks][4]
    unsigned aq[2][4][4];
#pragma unroll
    for (int mi = 0; mi < 2; mi++)
#pragma unroll
        for (int ks = 0; ks < 4; ks++) {
            int qr = mi * 16 + (lane >> 2);
            int dc = ks * 8 + (lane & 3);
            aq[mi][ks][0] = __float_as_uint(sQ[qr * QSTR + dc]);
            aq[mi][ks][1] = __float_as_uint(sQ[(qr + 8) * QSTR + dc]);
            aq[mi][ks][2] = __float_as_uint(sQ[qr * QSTR + dc + 4]);
            aq[mi][ks][3] = __float_as_uint(sQ[(qr + 8) * QSTR + dc + 4]);
        }

    // ---- phase A: S = Q^T K, tile over 8 key-chunks of 128
    for (int kt = 0; kt < 8; kt++) {
        __syncthreads();
        for (int i = tid; i < 4096; i += 256) {
            int d = i >> 7, key = i & 127;
            sK[key * KSTR + d] = to_tf32(kbase[d * HW + kt * 128 + key]);
        }
        __syncthreads();

        float cS[2][2][4];
#pragma unroll
        for (int mi = 0; mi < 2; mi++)
#pragma unroll
            for (int nj = 0; nj < 2; nj++)
#pragma unroll
                for (int q = 0; q < 4; q++) cS[mi][nj][q] = 0.f;

#pragma unroll
        for (int ks = 0; ks < 4; ks++) {
#pragma unroll
            for (int nj = 0; nj < 2; nj++) {
                int ncol = w * 16 + nj * 8 + (lane >> 2);
                unsigned bf[2];
                bf[0] = __float_as_uint(sK[ncol * KSTR + ks * 8 + (lane & 3)]);
                bf[1] = __float_as_uint(sK[ncol * KSTR + ks * 8 + (lane & 3) + 4]);
#pragma unroll
                for (int mi = 0; mi < 2; mi++)
                    mma_tf32(cS[mi][nj], aq[mi][ks], bf);
            }
        }
        // store scaled scores
#pragma unroll
        for (int mi = 0; mi < 2; mi++)
#pragma unroll
            for (int nj = 0; nj < 2; nj++) {
                int qr = mi * 16 + (lane >> 2);
                int kc = kt * 128 + w * 16 + nj * 8 + 2 * (lane & 3);
                sS[qr * SSTR + kc]           = cS[mi][nj][0] * scale;
                sS[qr * SSTR + kc + 1]       = cS[mi][nj][1] * scale;
                sS[(qr + 8) * SSTR + kc]     = cS[mi][nj][2] * scale;
                sS[(qr + 8) * SSTR + kc + 1] = cS[mi][nj][3] * scale;
            }
    }
    __syncthreads();

    // ---- phase B: softmax over keys; store tf32-rounded exp
#pragma unroll
    for (int r = 0; r < 4; r++) {
        int q = w * 4 + r;
        float* row = sS + q * SSTR;
        float mx = -1e30f;
        for (int m = lane; m < 1024; m += 32) mx = fmaxf(mx, row[m]);
#pragma unroll
        for (int off = 16; off; off >>= 1)
            mx = fmaxf(mx, __shfl_xor_sync(0xffffffffu, mx, off));
        float s = 0.f;
        for (int m = lane; m < 1024; m += 32) {
            float e = __expf(row[m] - mx);
            row[m] = to_tf32(e);
            s += e;
        }
#pragma unroll
        for (int off = 16; off; off >>= 1)
            s += __shfl_xor_sync(0xffffffffu, s, off);
        if (lane == 0) sInv[q] = 1.f / s;
    }

    // ---- phase C: O = P V  (warp-split keys, smem reduce)
    float cO[2][4][4];
#pragma unroll
    for (int mi = 0; mi < 2; mi++)
#pragma unroll
        for (int nd = 0; nd < 4; nd++)
#pragma unroll
            for (int q = 0; q < 4; q++) cO[mi][nd][q] = 0.f;

    for (int kt = 0; kt < 8; kt++) {
        __syncthreads();
        for (int i = tid * 4; i < 4096; i += 1024) {
            int d = i >> 7, key = i & 127;
            float4 v = *(const float4*)&vbase[d * HW + kt * 128 + key];
            float4 t;
            t.x = to_tf32(v.x); t.y = to_tf32(v.y);
            t.z = to_tf32(v.z); t.w = to_tf32(v.w);
            *(float4*)&sV[d * VSTR + key] = t;
        }
        __syncthreads();

#pragma unroll
        for (int ks = 0; ks < 2; ks++) {
            int kc = w * 16 + ks * 8 + (lane & 3);       // key within tile
            unsigned af[2][4];
#pragma unroll
            for (int mi = 0; mi < 2; mi++) {
                int qr = mi * 16 + (lane >> 2);
                int col = kt * 128 + kc;
                af[mi][0] = __float_as_uint(sS[qr * SSTR + col]);
                af[mi][1] = __float_as_uint(sS[(qr + 8) * SSTR + col]);
                af[mi][2] = __float_as_uint(sS[qr * SSTR + col + 4]);
                af[mi][3] = __float_as_uint(sS[(qr + 8) * SSTR + col + 4]);
            }
#pragma unroll
            for (int nd = 0; nd < 4; nd++) {
                int dc = nd * 8 + (lane >> 2);
                unsigned bf[2];
                bf[0] = __float_as_uint(sV[dc * VSTR + kc]);
                bf[1] = __float_as_uint(sV[dc * VSTR + kc + 4]);
#pragma unroll
                for (int mi = 0; mi < 2; mi++)
                    mma_tf32(cO[mi][nd], af[mi], bf);
            }
        }
    }

    // store warp partials
#pragma unroll
    for (int mi = 0; mi < 2; mi++)
#pragma unroll
        for (int nd = 0; nd < 4; nd++) {
            int q = mi * 16 + (lane >> 2);
            int d = nd * 8 + 2 * (lane & 3);
            sO[(w * 32 + q) * 33 + d]           = cO[mi][nd][0];
            sO[(w * 32 + q) * 33 + d + 1]       = cO[mi][nd][1];
            sO[(w * 32 + q + 8) * 33 + d]       = cO[mi][nd][2];
            sO[(w * 32 + q + 8) * 33 + d + 1]   = cO[mi][nd][3];
        }
    __syncthreads();

    // reduce 8 warp partials, normalize, write
    for (int i = tid; i < 1024; i += 256) {
        int q = i & 31, d = i >> 5;
        float s = 0.f;
#pragma unroll
        for (int ww = 0; ww < 8; ww++)
            s += sO[(ww * 32 + q) * 33 + d];
        out[((size_t)b * C + h * HDIM + d) * HW + n0 + q] = s * sInv[q];
    }
}

// ---------------- launch ----------------
extern "C" void kernel_launch(void* const* d_in, const int* in_sizes, int n_in,
                              void* d_out, int out_size)
{
    const float* x       = (const float*)d_in[0];
    const float* conv1_w = (const float*)d_in[1];
    const float* conv1_b = (const float*)d_in[2];
    const float* bn1_g   = (const float*)d_in[3];
    const float* bn1_b   = (const float*)d_in[4];
    const float* bn1_m   = (const float*)d_in[5];
    const float* bn1_v   = (const float*)d_in[6];
    const float* conv2_w = (const float*)d_in[7];
    const float* conv2_b = (const float*)d_in[8];
    const float* bn2_g   = (const float*)d_in[9];
    const float* bn2_b   = (const float*)d_in[10];
    const float* bn2_m   = (const float*)d_in[11];
    const float* bn2_v   = (const float*)d_in[12];
    const float* q_w     = (const float*)d_in[13];
    const float* q_b     = (const float*)d_in[14];
    const float* k_w     = (const float*)d_in[15];
    const float* k_b     = (const float*)d_in[16];
    const float* v_w     = (const float*)d_in[17];
    const float* v_b     = (const float*)d_in[18];
    const float* o_w     = (const float*)d_in[19];
    const float* o_b     = (const float*)d_in[20];
    const float* gate    = (const float*)d_in[21];
    float* out           = (float*)d_out;

    float *p_w1t, *p_w2t, *p_b1, *p_b2, *p_wqkv, *p_bqkv, *p_wot;
    float *p_t1, *p_conv, *p_qkv, *p_attn;
    cudaGetSymbolAddress((void**)&p_w1t,  g_w1t);
    cudaGetSymbolAddress((void**)&p_w2t,  g_w2t);
    cudaGetSymbolAddress((void**)&p_b1,   g_b1);
    cudaGetSymbolAddress((void**)&p_b2,   g_b2);
    cudaGetSymbolAddress((void**)&p_wqkv, g_wqkv);
    cudaGetSymbolAddress((void**)&p_bqkv, g_bqkv);
    cudaGetSymbolAddress((void**)&p_wot,  g_wot);
    cudaGetSymbolAddress((void**)&p_t1,   g_t1);
    cudaGetSymbolAddress((void**)&p_conv, g_conv);
    cudaGetSymbolAddress((void**)&p_qkv,  g_qkv);
    cudaGetSymbolAddress((void**)&p_attn, g_attn);

    // weight transform + BN fold
    prep_kernel<<<2048, 256>>>(conv1_w, conv1_b, bn1_g, bn1_b, bn1_m, bn1_v,
                               conv2_w, conv2_b, bn2_g, bn2_b, bn2_m, bn2_v,
                               q_w, q_b, k_w, k_b, v_w, v_b, o_w);

    // conv1 (3x3) + BN + relu -> t1
    dim3 gConv(M_TOTAL / BM, C / BN);
    gemm_k<1, 1><<<gConv, 256>>>(x, p_w1t, p_b1, p_t1, KCONV, C,
                                 nullptr, nullptr, nullptr);
    // conv2 (3x3) + BN -> conv_out
    gemm_k<1, 0><<<gConv, 256>>>(p_t1, p_w2t, p_b2, p_conv, KCONV, C,
                                 nullptr, nullptr, nullptr);
    // fused qkv (1x1) -> qkv buffer
    dim3 gQKV(M_TOTAL / BM, 768 / BN);
    gemm_k<0, 0><<<gQKV, 256>>>(x, p_wqkv, p_bqkv, p_qkv, C, 768,
                                nullptr, nullptr, nullptr);

    // attention
    const int attn_smem = (32 * SSTR + 32 * QSTR + 128 * KSTR + 32 * VSTR
                           + 8 * 32 * 33 + 32) * (int)sizeof(float);
    cudaFuncSetAttribute(attn_kernel, cudaFuncAttributeMaxDynamicSharedMemorySize,
                         attn_smem);
    dim3 gAttn(HW / 32, HEADS, BATCH);
    attn_kernel<<<gAttn, 256, attn_smem>>>(p_qkv, p_attn);

    // out-proj (1x1) + gate + conv residual + input residual + relu -> out
    dim3 gOut(M_TOTAL / BM, C / BN);
    gemm_k<0, 2><<<gOut, 256>>>(p_attn, p_wot, o_b, out, C, C,
                                p_conv, x, gate);
}

// round 4
// speedup vs baseline: 1.8683x; 1.0880x over previous
#include <cuda_runtime.h>
#include <cuda_bf16.h>
#include <cstdint>
#include <math.h>

// Problem constants
#define BATCH 16
#define C 256
#define HW 1024          // 32x32
#define HEADS 8
#define HDIM 32
#define M_TOTAL (BATCH * HW)   // 16384
#define KCONV (C * 9)          // 2304

// ---------------- scratch (static device globals; no runtime allocation) ---------
__device__ float g_w1t[KCONV * C];    // [K][N] bn1-folded conv1 weights (tf32)
__device__ float g_w2t[KCONV * C];
__device__ float g_b1[C];
__device__ float g_b2[C];
__device__ float g_wqkv[C * 768];     // [K=256][N=768] (q|k|v transposed, tf32)
__device__ float g_bqkv[768];
__device__ float g_wot[C * C];        // out_w transposed (tf32)
__device__ float g_t1[BATCH * C * HW];
__device__ float g_conv[BATCH * C * HW];
__device__ float g_qkv[BATCH * 768 * HW];
__device__ float g_attn[BATCH * C * HW];

// ---------------- helpers ----------------
__device__ __forceinline__ float to_tf32(float x) {
    float y;
    asm("cvt.rna.tf32.f32 %0, %1;" : "=f"(y) : "f"(x));
    return y;
}

__device__ __forceinline__ void mma_tf32(float* c, const unsigned* a, const unsigned* b) {
    asm volatile(
        "mma.sync.aligned.m16n8k8.row.col.f32.tf32.tf32.f32 "
        "{%0,%1,%2,%3}, {%4,%5,%6,%7}, {%8,%9}, {%0,%1,%2,%3};\n"
        : "+f"(c[0]), "+f"(c[1]), "+f"(c[2]), "+f"(c[3])
        : "r"(a[0]), "r"(a[1]), "r"(a[2]), "r"(a[3]), "r"(b[0]), "r"(b[1]));
}

__device__ __forceinline__ void cp16(uint32_t s, const void* g) {
    asm volatile("cp.async.cg.shared.global [%0], [%1], 16;" :: "r"(s), "l"(g));
}
__device__ __forceinline__ void cp4_pred(uint32_t s, const void* g, bool ok) {
    int sz = ok ? 4 : 0;
    asm volatile("cp.async.ca.shared.global [%0], [%1], 4, %2;" :: "r"(s), "l"(g), "r"(sz));
}
__device__ __forceinline__ void cp_commit() { asm volatile("cp.async.commit_group;"); }
template<int N> __device__ __forceinline__ void cp_wait() {
    asm volatile("cp.async.wait_group %0;" :: "n"(N));
}

// fast exp on the FMA pipe (avoids MUFU throughput wall). x <= 0 expected.
__device__ __forceinline__ float fast_exp(float x) {
    float t = x * 1.4426950408889634f;
    t = fmaxf(t, -126.0f);
    float fi = floorf(t);
    float f = t - fi;
    float p = fmaf(f, 0.0015041f, 0.0096181f);
    p = fmaf(f, p, 0.0555041f);
    p = fmaf(f, p, 0.2402265f);
    p = fmaf(f, p, 0.6931472f);
    p = fmaf(f, p, 1.0f);
    int e = (int)fi;
    return p * __int_as_float((e + 127) << 23);
}

// ---------------- weight transform + BN fold ----------------
__global__ void prep_kernel(
    const float* __restrict__ conv1_w, const float* __restrict__ conv1_b,
    const float* __restrict__ g1, const float* __restrict__ be1,
    const float* __restrict__ m1, const float* __restrict__ v1,
    const float* __restrict__ conv2_w, const float* __restrict__ conv2_b,
    const float* __restrict__ g2, const float* __restrict__ be2,
    const float* __restrict__ m2, const float* __restrict__ v2,
    const float* __restrict__ q_w, const float* __restrict__ q_b,
    const float* __restrict__ k_w, const float* __restrict__ k_b,
    const float* __restrict__ v_w, const float* __restrict__ v_b,
    const float* __restrict__ o_w)
{
    const int W1T_N = KCONV * C;          // 589824
    const int QKV_N = C * 768;            // 196608
    const int WOT_N = C * C;              // 65536
    const int total = 2 * W1T_N + QKV_N + WOT_N + 768 + 512;
    for (int i = blockIdx.x * blockDim.x + threadIdx.x; i < total;
         i += gridDim.x * blockDim.x) {
        if (i < W1T_N) {
            int k = i >> 8, o = i & 255;
            int c = k / 9, r = k - c * 9;
            float s = g1[o] * rsqrtf(v1[o] + 1e-5f);
            g_w1t[i] = to_tf32(conv1_w[(o * C + c) * 9 + r] * s);
        } else if (i < 2 * W1T_N) {
            int j = i - W1T_N;
            int k = j >> 8, o = j & 255;
            int c = k / 9, r = k - c * 9;
            float s = g2[o] * rsqrtf(v2[o] + 1e-5f);
            g_w2t[j] = to_tf32(conv2_w[(o * C + c) * 9 + r] * s);
        } else if (i < 2 * W1T_N + QKV_N) {
            int j = i - 2 * W1T_N;
            int c = j / 768, n = j - c * 768;
            float w;
            if (n < 256)      w = q_w[n * C + c];
            else if (n < 512) w = k_w[(n - 256) * C + c];
            else              w = v_w[(n - 512) * C + c];
            g_wqkv[j] = to_tf32(w);
        } else if (i < 2 * W1T_N + QKV_N + WOT_N) {
            int j = i - (2 * W1T_N + QKV_N);
            int c = j >> 8, o = j & 255;
            g_wot[j] = to_tf32(o_w[o * C + c]);
        } else if (i < 2 * W1T_N + QKV_N + WOT_N + 768) {
            int n = i - (2 * W1T_N + QKV_N + WOT_N);
            float bb;
            if (n < 256)      bb = q_b[n];
            else if (n < 512) bb = k_b[n - 256];
            else              bb = v_b[n - 512];
            g_bqkv[n] = bb;
        } else {
            int j = i - (2 * W1T_N + QKV_N + WOT_N + 768); // 0..511
            int o = j & 255;
            if (j < 256) {
                float s = g1[o] * rsqrtf(v1[o] + 1e-5f);
                g_b1[o] = conv1_b[o] * s + be1[o] - m1[o] * s;
            } else {
                float s = g2[o] * rsqrtf(v2[o] + 1e-5f);
                g_b2[o] = conv2_b[o] * s + be2[o] - m2[o] * s;
            }
        }
    }
}

// ---------------- TF32 tensor-core GEMM, cp.async double-buffered ----------------
// MODE 0: A is [B, Cin, HW], K = Cin (1x1 conv)
// MODE 1: A is [B, Cin, 32, 32], K = Cin*9 (3x3 conv, SAME padding)
// EPI 0: out = acc + bias
// EPI 1: out = relu(acc + bias)
// EPI 2: out = relu(conv + sigmoid(gate)*(acc + bias) + resid)
// ROUND: tf32-round output before store (for GEMM-consumed intermediates)
#define BM 128
#define BN 128
#define BKT 16
#define AMS 136   // 136 % 32 = 8 -> conflict-free fragment LDS
#define STAGE_F (BKT * AMS)   // floats per stage per matrix = 2176

template<int MODE, int EPI, int ROUND>
__global__ void __launch_bounds__(256, 2) gemm_k(
    const float* __restrict__ A, const float* __restrict__ Bw,
    const float* __restrict__ bias, float* __restrict__ Cout,
    int Kdim, int Ndim,
    const float* __restrict__ convres, const float* __restrict__ resid,
    const float* __restrict__ gp)
{
    __shared__ float sA[2 * STAGE_F];
    __shared__ float sB[2 * STAGE_F];

    const int tid  = threadIdx.x;
    const int lane = tid & 31;
    const int wid  = tid >> 5;
    const int wm   = wid & 1;        // m offset 64*wm
    const int wn   = wid >> 1;       // n offset 32*wn
    const int m0 = blockIdx.x * BM;
    const int n0 = blockIdx.y * BN;
    const int bq = m0 >> 10;
    const int p0 = m0 & 1023;

    const int sk  = tid >> 4;        // k row 0..15
    const int sm8 = (tid & 15) * 8;  // 8-float chunk base

    const uint32_t saA = (uint32_t)__cvta_generic_to_shared(sA);
    const uint32_t saB = (uint32_t)__cvta_generic_to_shared(sB);

    float acc[4][4][4];
#pragma unroll
    for (int i = 0; i < 4; i++)
#pragma unroll
        for (int j = 0; j < 4; j++)
#pragma unroll
            for (int q = 0; q < 4; q++) acc[i][j][q] = 0.f;

    const int nt = Kdim / BKT;

    auto stage = [&](int t, int st) {
        const int k = t * BKT + sk;
        uint32_t da = saA + (uint32_t)(st * STAGE_F + sk * AMS + sm8) * 4u;
        if (MODE == 0) {
            const float* ga = A + (((size_t)bq * C + k) << 10) + p0 + sm8;
            cp16(da, ga);
            cp16(da + 16, ga + 4);
        } else {
            int c = k / 9, r = k - c * 9;
            int dy = r / 3 - 1, dx = (r % 3) - 1;
            const float* base = A + (((size_t)bq * C + c) << 10);
#pragma unroll
            for (int i = 0; i < 8; i++) {
                int p = p0 + sm8 + i;
                int y = (p >> 5) + dy;
                int x = (p & 31) + dx;
                bool ok = ((unsigned)y < 32u) & ((unsigned)x < 32u);
                const float* g = ok ? (base + (y << 5) + x) : A;
                cp4_pred(da + (uint32_t)i * 4u, g, ok);
            }
        }
        uint32_t db = saB + (uint32_t)(st * STAGE_F + sk * AMS + sm8) * 4u;
        const float* gb = Bw + (size_t)k * Ndim + n0 + sm8;
        cp16(db, gb);
        cp16(db + 16, gb + 4);
    };

    stage(0, 0);
    cp_commit();

    for (int t = 0; t < nt; t++) {
        const int cur = t & 1;
        if (t + 1 < nt) {
            stage(t + 1, cur ^ 1);
            cp_commit();
            cp_wait<1>();
        } else {
            cp_wait<0>();
        }
        __syncthreads();

        const float* fA = sA + cur * STAGE_F;
        const float* fB = sB + cur * STAGE_F;
#pragma unroll
        for (int ks = 0; ks < 2; ks++) {
            const int kc = ks * 8 + (lane & 3);
            unsigned af[4][4], bf[4][2];
#pragma unroll
            for (int mi = 0; mi < 4; mi++) {
                int ar = wm * 64 + mi * 16 + (lane >> 2);
                af[mi][0] = __float_as_uint(fA[kc * AMS + ar]);
                af[mi][1] = __float_as_uint(fA[kc * AMS + ar + 8]);
                af[mi][2] = __float_as_uint(fA[(kc + 4) * AMS + ar]);
                af[mi][3] = __float_as_uint(fA[(kc + 4) * AMS + ar + 8]);
            }
#pragma unroll
            for (int nj = 0; nj < 4; nj++) {
                int br = wn * 32 + nj * 8 + (lane >> 2);
                bf[nj][0] = __float_as_uint(fB[kc * AMS + br]);
                bf[nj][1] = __float_as_uint(fB[(kc + 4) * AMS + br]);
            }
#pragma unroll
            for (int mi = 0; mi < 4; mi++)
#pragma unroll
                for (int nj = 0; nj < 4; nj++)
                    mma_tf32(acc[mi][nj], af[mi], bf[nj]);
        }
        __syncthreads();
    }

    // ---- epilogue
    float sg = 0.f;
    if (EPI == 2) sg = 1.f / (1.f + __expf(-gp[0]));
#pragma unroll
    for (int mi = 0; mi < 4; mi++) {
#pragma unroll
        for (int half = 0; half < 2; half++) {
            int m = m0 + wm * 64 + mi * 16 + (lane >> 2) + half * 8;
            int mb = m >> 10, p = m & 1023;
#pragma unroll
            for (int nj = 0; nj < 4; nj++) {
                int n = n0 + wn * 32 + nj * 8 + 2 * (lane & 3);
                float v0 = acc[mi][nj][half * 2 + 0] + bias[n];
                float v1 = acc[mi][nj][half * 2 + 1] + bias[n + 1];
                size_t addr = (((size_t)mb * Ndim + n) << 10) + p;
                if (EPI == 1) {
                    v0 = fmaxf(v0, 0.f); v1 = fmaxf(v1, 0.f);
                } else if (EPI == 2) {
                    float c0 = convres[addr], c1 = convres[addr + 1024];
                    float r0 = resid[addr],   r1 = resid[addr + 1024];
                    v0 = fmaxf(c0 + sg * v0 + r0, 0.f);
                    v1 = fmaxf(c1 + sg * v1 + r1, 0.f);
                }
                if (ROUND) { v0 = to_tf32(v0); v1 = to_tf32(v1); }
                Cout[addr]        = v0;
                Cout[addr + 1024] = v1;
            }
        }
    }
}

// ---------------- attention kernel (TF32 mma + fast exp) ----------------
#define SSTR 1044   // 1044 % 32 = 20 -> conflict-free P-frag loads
#define QSTR 36     // sQ [q][d]
#define KSTR 33     // sK [key][d]
#define VSTR 132    // sV [d][key]

__global__ void __launch_bounds__(256, 1) attn_kernel(
    const float* __restrict__ qkv, float* __restrict__ out)
{
    extern __shared__ float sm[];
    float* sS   = sm;                    // [32][SSTR]
    float* sQ   = sS + 32 * SSTR;        // [32][QSTR]
    float* sK   = sQ + 32 * QSTR;        // [128][KSTR]
    float* sV   = sK + 128 * KSTR;       // [32][VSTR]
    float* sO   = sV + 32 * VSTR;        // [8][32][33]
    float* sInv = sO + 8 * 32 * 33;      // [32]

    const int tid  = threadIdx.x;
    const int lane = tid & 31;
    const int w    = tid >> 5;
    const int n0 = blockIdx.x * 32;
    const int h  = blockIdx.y;
    const int b  = blockIdx.z;

    const float* qbase = qkv + ((size_t)b * 768 + h * HDIM) * HW;
    const float* kbase = qbase + 256 * HW;
    const float* vbase = qbase + 512 * HW;
    const float scale = 0.17677669529663687f;  // 1/sqrt(32)

    // ---- stage Q (already tf32-rounded by producer)
    for (int i = tid; i < 1024; i += 256) {
        int d = i >> 5, q = i & 31;
        sQ[q * QSTR + d] = qbase[d * HW + n0 + q];
    }
    __syncthreads();

    unsigned aq[2][4][4];
#pragma unroll
    for (int mi = 0; mi < 2; mi++)
#pragma unroll
        for (int ks = 0; ks < 4; ks++) {
            int qr = mi * 16 + (lane >> 2);
            int dc = ks * 8 + (lane & 3);
            aq[mi][ks][0] = __float_as_uint(sQ[qr * QSTR + dc]);
            aq[mi][ks][1] = __float_as_uint(sQ[(qr + 8) * QSTR + dc]);
            aq[mi][ks][2] = __float_as_uint(sQ[qr * QSTR + dc + 4]);
            aq[mi][ks][3] = __float_as_uint(sQ[(qr + 8) * QSTR + dc + 4]);
        }

    // ---- phase A: S = Q^T K
    for (int kt = 0; kt < 8; kt++) {
        __syncthreads();
        for (int i = tid; i < 4096; i += 256) {
            int d = i >> 7, key = i & 127;
            sK[key * KSTR + d] = kbase[d * HW + kt * 128 + key];
        }
        __syncthreads();

        float cS[2][2][4];
#pragma unroll
        for (int mi = 0; mi < 2; mi++)
#pragma unroll
            for (int nj = 0; nj < 2; nj++)
#pragma unroll
                for (int q = 0; q < 4; q++) cS[mi][nj][q] = 0.f;

#pragma unroll
        for (int ks = 0; ks < 4; ks++) {
#pragma unroll
            for (int nj = 0; nj < 2; nj++) {
                int ncol = w * 16 + nj * 8 + (lane >> 2);
                unsigned bf[2];
                bf[0] = __float_as_uint(sK[ncol * KSTR + ks * 8 + (lane & 3)]);
                bf[1] = __float_as_uint(sK[ncol * KSTR + ks * 8 + (lane & 3) + 4]);
#pragma unroll
                for (int mi = 0; mi < 2; mi++)
                    mma_tf32(cS[mi][nj], aq[mi][ks], bf);
            }
        }
#pragma unroll
        for (int mi = 0; mi < 2; mi++)
#pragma unroll
            for (int nj = 0; nj < 2; nj++) {
                int qr = mi * 16 + (lane >> 2);
                int kc = kt * 128 + w * 16 + nj * 8 + 2 * (lane & 3);
                sS[qr * SSTR + kc]           = cS[mi][nj][0] * scale;
                sS[qr * SSTR + kc + 1]       = cS[mi][nj][1] * scale;
                sS[(qr + 8) * SSTR + kc]     = cS[mi][nj][2] * scale;
                sS[(qr + 8) * SSTR + kc + 1] = cS[mi][nj][3] * scale;
            }
    }
    __syncthreads();

    // ---- phase B: softmax over keys (fast_exp on FMA pipe)
#pragma unroll
    for (int r = 0; r < 4; r++) {
        int q = w * 4 + r;
        float* row = sS + q * SSTR;
        float mx = -1e30f;
        for (int m = lane; m < 1024; m += 32) mx = fmaxf(mx, row[m]);
#pragma unroll
        for (int off = 16; off; off >>= 1)
            mx = fmaxf(mx, __shfl_xor_sync(0xffffffffu, mx, off));
        float s = 0.f;
        for (int m = lane; m < 1024; m += 32) {
            float e = fast_exp(row[m] - mx);
            row[m] = e;
            s += e;
        }
#pragma unroll
        for (int off = 16; off; off >>= 1)
            s += __shfl_xor_sync(0xffffffffu, s, off);
        if (lane == 0) sInv[q] = 1.f / s;
    }

    // ---- phase C: O = P V (warp-split keys, smem reduce)
    float cO[2][4][4];
#pragma unroll
    for (int mi = 0; mi < 2; mi++)
#pragma unroll
        for (int nd = 0; nd < 4; nd++)
#pragma unroll
            for (int q = 0; q < 4; q++) cO[mi][nd][q] = 0.f;

    for (int kt = 0; kt < 8; kt++) {
        __syncthreads();
        for (int i = tid * 4; i < 4096; i += 1024) {
            int d = i >> 7, key = i & 127;
            *(float4*)&sV[d * VSTR + key] =
                *(const float4*)&vbase[d * HW + kt * 128 + key];
        }
        __syncthreads();

#pragma unroll
        for (int ks = 0; ks < 2; ks++) {
            int kc = w * 16 + ks * 8 + (lane & 3);
            unsigned af[2][4];
#pragma unroll
            for (int mi = 0; mi < 2; mi++) {
                int qr = mi * 16 + (lane >> 2);
                int col = kt * 128 + kc;
                af[mi][0] = __float_as_uint(sS[qr * SSTR + col]);
                af[mi][1] = __float_as_uint(sS[(qr + 8) * SSTR + col]);
                af[mi][2] = __float_as_uint(sS[qr * SSTR + col + 4]);
                af[mi][3] = __float_as_uint(sS[(qr + 8) * SSTR + col + 4]);
            }
#pragma unroll
            for (int nd = 0; nd < 4; nd++) {
                int dc = nd * 8 + (lane >> 2);
                unsigned bf[2];
                bf[0] = __float_as_uint(sV[dc * VSTR + kc]);
                bf[1] = __float_as_uint(sV[dc * VSTR + kc + 4]);
#pragma unroll
                for (int mi = 0; mi < 2; mi++)
                    mma_tf32(cO[mi][nd], af[mi], bf);
            }
        }
    }

#pragma unroll
    for (int mi = 0; mi < 2; mi++)
#pragma unroll
        for (int nd = 0; nd < 4; nd++) {
            int q = mi * 16 + (lane >> 2);
            int d = nd * 8 + 2 * (lane & 3);
            sO[(w * 32 + q) * 33 + d]           = cO[mi][nd][0];
            sO[(w * 32 + q) * 33 + d + 1]       = cO[mi][nd][1];
            sO[(w * 32 + q + 8) * 33 + d]       = cO[mi][nd][2];
            sO[(w * 32 + q + 8) * 33 + d + 1]   = cO[mi][nd][3];
        }
    __syncthreads();

    for (int i = tid; i < 1024; i += 256) {
        int q = i & 31, d = i >> 5;
        float s = 0.f;
#pragma unroll
        for (int ww = 0; ww < 8; ww++)
            s += sO[(ww * 32 + q) * 33 + d];
        out[((size_t)b * C + h * HDIM + d) * HW + n0 + q] = to_tf32(s * sInv[q]);
    }
}

// ---------------- launch ----------------
extern "C" void kernel_launch(void* const* d_in, const int* in_sizes, int n_in,
                              void* d_out, int out_size)
{
    const float* x       = (const float*)d_in[0];
    const float* conv1_w = (const float*)d_in[1];
    const float* conv1_b = (const float*)d_in[2];
    const float* bn1_g   = (const float*)d_in[3];
    const float* bn1_b   = (const float*)d_in[4];
    const float* bn1_m   = (const float*)d_in[5];
    const float* bn1_v   = (const float*)d_in[6];
    const float* conv2_w = (const float*)d_in[7];
    const float* conv2_b = (const float*)d_in[8];
    const float* bn2_g   = (const float*)d_in[9];
    const float* bn2_b   = (const float*)d_in[10];
    const float* bn2_m   = (const float*)d_in[11];
    const float* bn2_v   = (const float*)d_in[12];
    const float* q_w     = (const float*)d_in[13];
    const float* q_b     = (const float*)d_in[14];
    const float* k_w     = (const float*)d_in[15];
    const float* k_b     = (const float*)d_in[16];
    const float* v_w     = (const float*)d_in[17];
    const float* v_b     = (const float*)d_in[18];
    const float* o_w     = (const float*)d_in[19];
    const float* o_b     = (const float*)d_in[20];
    const float* gate    = (const float*)d_in[21];
    float* out           = (float*)d_out;

    float *p_w1t, *p_w2t, *p_b1, *p_b2, *p_wqkv, *p_bqkv, *p_wot;
    float *p_t1, *p_conv, *p_qkv, *p_attn;
    cudaGetSymbolAddress((void**)&p_w1t,  g_w1t);
    cudaGetSymbolAddress((void**)&p_w2t,  g_w2t);
    cudaGetSymbolAddress((void**)&p_b1,   g_b1);
    cudaGetSymbolAddress((void**)&p_b2,   g_b2);
    cudaGetSymbolAddress((void**)&p_wqkv, g_wqkv);
    cudaGetSymbolAddress((void**)&p_bqkv, g_bqkv);
    cudaGetSymbolAddress((void**)&p_wot,  g_wot);
    cudaGetSymbolAddress((void**)&p_t1,   g_t1);
    cudaGetSymbolAddress((void**)&p_conv, g_conv);
    cudaGetSymbolAddress((void**)&p_qkv,  g_qkv);
    cudaGetSymbolAddress((void**)&p_attn, g_attn);

    // weight transform + BN fold
    prep_kernel<<<1024, 256>>>(conv1_w, conv1_b, bn1_g, bn1_b, bn1_m, bn1_v,
                               conv2_w, conv2_b, bn2_g, bn2_b, bn2_m, bn2_v,
                               q_w, q_b, k_w, k_b, v_w, v_b, o_w);

    // conv1 (3x3) + BN + relu -> t1 (tf32-rounded)
    dim3 gConv(M_TOTAL / BM, C / BN);
    gemm_k<1, 1, 1><<<gConv, 256>>>(x, p_w1t, p_b1, p_t1, KCONV, C,
                                    nullptr, nullptr, nullptr);
    // conv2 (3x3) + BN -> conv_out (exact)
    gemm_k<1, 0, 0><<<gConv, 256>>>(p_t1, p_w2t, p_b2, p_conv, KCONV, C,
                                    nullptr, nullptr, nullptr);
    // fused qkv (1x1) -> qkv buffer (tf32-rounded)
    dim3 gQKV(M_TOTAL / BM, 768 / BN);
    gemm_k<0, 0, 1><<<gQKV, 256>>>(x, p_wqkv, p_bqkv, p_qkv, C, 768,
                                   nullptr, nullptr, nullptr);

    // attention
    const int attn_smem = (32 * SSTR + 32 * QSTR + 128 * KSTR + 32 * VSTR
                           + 8 * 32 * 33 + 32) * (int)sizeof(float);
    cudaFuncSetAttribute(attn_kernel, cudaFuncAttributeMaxDynamicSharedMemorySize,
                         attn_smem);
    dim3 gAttn(HW / 32, HEADS, BATCH);
    attn_kernel<<<gAttn, 256, attn_smem>>>(p_qkv, p_attn);

    // out-proj (1x1) + gate + conv residual + input residual + relu -> out
    dim3 gOut(M_TOTAL / BM, C / BN);
    gemm_k<0, 2, 0><<<gOut, 256>>>(p_attn, p_wot, o_b, out, C, C,
                                   p_conv, x, gate);
}

// round 5
// speedup vs baseline: 2.1879x; 1.1710x over previous
#include <cuda_runtime.h>
#include <cuda_bf16.h>
#include <cstdint>
#include <math.h>

// Problem constants
#define BATCH 16
#define C 256
#define HW 1024          // 32x32
#define HEADS 8
#define HDIM 32
#define M_TOTAL (BATCH * HW)   // 16384
#define KCONV (C * 9)          // 2304

// ---------------- scratch (static device globals; no runtime allocation) ---------
__device__ float g_w1t[KCONV * C];    // [r][c][n] bn1-folded conv1 weights (tf32)
__device__ float g_w2t[KCONV * C];
__device__ float g_b1[C];
__device__ float g_b2[C];
__device__ float g_wqkv[C * 768];     // [K=256][N=768] (q|k|v transposed, tf32)
__device__ float g_bqkv[768];
__device__ float g_wot[C * C];        // out_w transposed (tf32)
__device__ float g_t1[BATCH * C * HW];
__device__ float g_conv[BATCH * C * HW];
__device__ float g_qkv[BATCH * 768 * HW];
__device__ float g_attn[BATCH * C * HW];

// ---------------- helpers ----------------
__device__ __forceinline__ float to_tf32(float x) {
    float y;
    asm("cvt.rna.tf32.f32 %0, %1;" : "=f"(y) : "f"(x));
    return y;
}

__device__ __forceinline__ void mma_tf32(float* c, const unsigned* a, const unsigned* b) {
    asm volatile(
        "mma.sync.aligned.m16n8k8.row.col.f32.tf32.tf32.f32 "
        "{%0,%1,%2,%3}, {%4,%5,%6,%7}, {%8,%9}, {%0,%1,%2,%3};\n"
        : "+f"(c[0]), "+f"(c[1]), "+f"(c[2]), "+f"(c[3])
        : "r"(a[0]), "r"(a[1]), "r"(a[2]), "r"(a[3]), "r"(b[0]), "r"(b[1]));
}

__device__ __forceinline__ void cp16(uint32_t s, const void* g) {
    asm volatile("cp.async.cg.shared.global [%0], [%1], 16;" :: "r"(s), "l"(g));
}
// predicated 16B: src-size 0 -> zero-fill 16 bytes
__device__ __forceinline__ void cp16_pred(uint32_t s, const void* g, bool ok) {
    int sz = ok ? 16 : 0;
    asm volatile("cp.async.cg.shared.global [%0], [%1], 16, %2;" :: "r"(s), "l"(g), "r"(sz));
}
__device__ __forceinline__ void cp_commit() { asm volatile("cp.async.commit_group;"); }
template<int N> __device__ __forceinline__ void cp_wait() {
    asm volatile("cp.async.wait_group %0;" :: "n"(N));
}

// fast exp on the FMA pipe (avoids MUFU throughput wall). x <= 0 expected.
__device__ __forceinline__ float fast_exp(float x) {
    float t = x * 1.4426950408889634f;
    t = fmaxf(t, -126.0f);
    float fi = floorf(t);
    float f = t - fi;
    float p = fmaf(f, 0.0015041f, 0.0096181f);
    p = fmaf(f, p, 0.0555041f);
    p = fmaf(f, p, 0.2402265f);
    p = fmaf(f, p, 0.6931472f);
    p = fmaf(f, p, 1.0f);
    int e = (int)fi;
    return p * __int_as_float((e + 127) << 23);
}

// ---------------- weight transform + BN fold ----------------
__global__ void prep_kernel(
    const float* __restrict__ conv1_w, const float* __restrict__ conv1_b,
    const float* __restrict__ g1, const float* __restrict__ be1,
    const float* __restrict__ m1, const float* __restrict__ v1,
    const float* __restrict__ conv2_w, const float* __restrict__ conv2_b,
    const float* __restrict__ g2, const float* __restrict__ be2,
    const float* __restrict__ m2, const float* __restrict__ v2,
    const float* __restrict__ q_w, const float* __restrict__ q_b,
    const float* __restrict__ k_w, const float* __restrict__ k_b,
    const float* __restrict__ v_w, const float* __restrict__ v_b,
    const float* __restrict__ o_w)
{
    const int W1T_N = KCONV * C;          // 589824
    const int QKV_N = C * 768;            // 196608
    const int WOT_N = C * C;              // 65536
    const int total = 2 * W1T_N + QKV_N + WOT_N + 768 + 512;
    for (int i = blockIdx.x * blockDim.x + threadIdx.x; i < total;
         i += gridDim.x * blockDim.x) {
        if (i < W1T_N) {
            int k = i >> 8, o = i & 255;       // k = r*256 + c
            int r = k >> 8, c = k & 255;
            float s = g1[o] * rsqrtf(v1[o] + 1e-5f);
            g_w1t[i] = to_tf32(conv1_w[(o * C + c) * 9 + r] * s);
        } else if (i < 2 * W1T_N) {
            int j = i - W1T_N;
            int k = j >> 8, o = j & 255;
            int r = k >> 8, c = k & 255;
            float s = g2[o] * rsqrtf(v2[o] + 1e-5f);
            g_w2t[j] = to_tf32(conv2_w[(o * C + c) * 9 + r] * s);
        } else if (i < 2 * W1T_N + QKV_N) {
            int j = i - 2 * W1T_N;
            int c = j / 768, n = j - c * 768;
            float w;
            if (n < 256)      w = q_w[n * C + c];
            else if (n < 512) w = k_w[(n - 256) * C + c];
            else              w = v_w[(n - 512) * C + c];
            g_wqkv[j] = to_tf32(w);
        } else if (i < 2 * W1T_N + QKV_N + WOT_N) {
            int j = i - (2 * W1T_N + QKV_N);
            int c = j >> 8, o = j & 255;
            g_wot[j] = to_tf32(o_w[o * C + c]);
        } else if (i < 2 * W1T_N + QKV_N + WOT_N + 768) {
            int n = i - (2 * W1T_N + QKV_N + WOT_N);
            float bb;
            if (n < 256)      bb = q_b[n];
            else if (n < 512) bb = k_b[n - 256];
            else              bb = v_b[n - 512];
            g_bqkv[n] = bb;
        } else {
            int j = i - (2 * W1T_N + QKV_N + WOT_N + 768); // 0..511
            int o = j & 255;
            if (j < 256) {
                float s = g1[o] * rsqrtf(v1[o] + 1e-5f);
                g_b1[o] = conv1_b[o] * s + be1[o] - m1[o] * s;
            } else {
                float s = g2[o] * rsqrtf(v2[o] + 1e-5f);
                g_b2[o] = conv2_b[o] * s + be2[o] - m2[o] * s;
            }
        }
    }
}

// ---------------- common tile params ----------------
#define BM 128
#define BN 128
#define BKT 16
#define AMS 136   // 136 % 32 = 8 -> conflict-free fragment LDS
#define STAGE_F (BKT * AMS)   // floats per stage per matrix = 2176

// ---------------- 1x1 TF32 GEMM (qkv / out-proj) ----------------
// EPI 0: out = acc + bias
// EPI 2: out = relu(conv + sigmoid(gate)*(acc + bias) + resid)
template<int EPI, int ROUND>
__global__ void __launch_bounds__(256, 2) gemm_k(
    const float* __restrict__ A, const float* __restrict__ Bw,
    const float* __restrict__ bias, float* __restrict__ Cout,
    int Kdim, int Ndim,
    const float* __restrict__ convres, const float* __restrict__ resid,
    const float* __restrict__ gp)
{
    __shared__ float sA[2 * STAGE_F];
    __shared__ float sB[2 * STAGE_F];

    const int tid  = threadIdx.x;
    const int lane = tid & 31;
    const int wid  = tid >> 5;
    const int wm   = wid & 1;
    const int wn   = wid >> 1;
    const int m0 = blockIdx.x * BM;
    const int n0 = blockIdx.y * BN;
    const int bq = m0 >> 10;
    const int p0 = m0 & 1023;

    const int sk  = tid >> 4;
    const int sm8 = (tid & 15) * 8;

    const uint32_t saA = (uint32_t)__cvta_generic_to_shared(sA);
    const uint32_t saB = (uint32_t)__cvta_generic_to_shared(sB);

    float acc[4][4][4];
#pragma unroll
    for (int i = 0; i < 4; i++)
#pragma unroll
        for (int j = 0; j < 4; j++)
#pragma unroll
            for (int q = 0; q < 4; q++) acc[i][j][q] = 0.f;

    const int nt = Kdim / BKT;

    auto stage = [&](int t, int st) {
        const int k = t * BKT + sk;
        uint32_t da = saA + (uint32_t)(st * STAGE_F + sk * AMS + sm8) * 4u;
        const float* ga = A + (((size_t)bq * C + k) << 10) + p0 + sm8;
        cp16(da, ga);
        cp16(da + 16, ga + 4);
        uint32_t db = saB + (uint32_t)(st * STAGE_F + sk * AMS + sm8) * 4u;
        const float* gb = Bw + (size_t)k * Ndim + n0 + sm8;
        cp16(db, gb);
        cp16(db + 16, gb + 4);
    };

    stage(0, 0);
    cp_commit();

    for (int t = 0; t < nt; t++) {
        const int cur = t & 1;
        if (t + 1 < nt) {
            stage(t + 1, cur ^ 1);
            cp_commit();
            cp_wait<1>();
        } else {
            cp_wait<0>();
        }
        __syncthreads();

        const float* fA = sA + cur * STAGE_F;
        const float* fB = sB + cur * STAGE_F;
#pragma unroll
        for (int ks = 0; ks < 2; ks++) {
            const int kc = ks * 8 + (lane & 3);
            unsigned af[4][4], bf[4][2];
#pragma unroll
            for (int mi = 0; mi < 4; mi++) {
                int ar = wm * 64 + mi * 16 + (lane >> 2);
                af[mi][0] = __float_as_uint(fA[kc * AMS + ar]);
                af[mi][1] = __float_as_uint(fA[kc * AMS + ar + 8]);
                af[mi][2] = __float_as_uint(fA[(kc + 4) * AMS + ar]);
                af[mi][3] = __float_as_uint(fA[(kc + 4) * AMS + ar + 8]);
            }
#pragma unroll
            for (int nj = 0; nj < 4; nj++) {
                int br = wn * 32 + nj * 8 + (lane >> 2);
                bf[nj][0] = __float_as_uint(fB[kc * AMS + br]);
                bf[nj][1] = __float_as_uint(fB[(kc + 4) * AMS + br]);
            }
#pragma unroll
            for (int mi = 0; mi < 4; mi++)
#pragma unroll
                for (int nj = 0; nj < 4; nj++)
                    mma_tf32(acc[mi][nj], af[mi], bf[nj]);
        }
        __syncthreads();
    }

    float sg = 0.f;
    if (EPI == 2) sg = 1.f / (1.f + __expf(-gp[0]));
#pragma unroll
    for (int mi = 0; mi < 4; mi++) {
#pragma unroll
        for (int half = 0; half < 2; half++) {
            int m = m0 + wm * 64 + mi * 16 + (lane >> 2) + half * 8;
            int mb = m >> 10, p = m & 1023;
#pragma unroll
            for (int nj = 0; nj < 4; nj++) {
                int n = n0 + wn * 32 + nj * 8 + 2 * (lane & 3);
                float v0 = acc[mi][nj][half * 2 + 0] + bias[n];
                float v1 = acc[mi][nj][half * 2 + 1] + bias[n + 1];
                size_t addr = (((size_t)mb * Ndim + n) << 10) + p;
                if (EPI == 2) {
                    float c0 = convres[addr], c1 = convres[addr + 1024];
                    float r0 = resid[addr],   r1 = resid[addr + 1024];
                    v0 = fmaxf(c0 + sg * v0 + r0, 0.f);
                    v1 = fmaxf(c1 + sg * v1 + r1, 0.f);
                }
                if (ROUND) { v0 = to_tf32(v0); v1 = to_tf32(v1); }
                Cout[addr]        = v0;
                Cout[addr + 1024] = v1;
            }
        }
    }
}

// ---------------- conv3x3 as 9 shifted 1x1 GEMMs ----------------
// Weights Bw laid out [r*256 + c][n]. 144 k-steps of 16 channels; per step the
// A tile is row-shifted (dy) contiguous loads, dx applied at fragment-load time.
// EPI 1: relu(acc+bias)   EPI 0: acc+bias
template<int EPI, int ROUND>
__global__ void __launch_bounds__(256, 2) convgemm_k(
    const float* __restrict__ A, const float* __restrict__ Bw,
    const float* __restrict__ bias, float* __restrict__ Cout)
{
    __shared__ float sAraw[2 * STAGE_F + 8];
    __shared__ float sB[2 * STAGE_F];
    float* sA = sAraw + 4;   // guard for ar-1 reads

    const int tid  = threadIdx.x;
    const int lane = tid & 31;
    const int wid  = tid >> 5;
    const int wm   = wid & 1;
    const int wn   = wid >> 1;
    const int m0 = blockIdx.x * BM;
    const int n0 = blockIdx.y * BN;
    const int bq = m0 >> 10;
    const int p0 = m0 & 1023;

    const int sk  = tid >> 4;        // channel within 16-tile
    const int sm8 = (tid & 15) * 8;

    const uint32_t saA = (uint32_t)__cvta_generic_to_shared(sA);
    const uint32_t saB = (uint32_t)__cvta_generic_to_shared(sB);

    float acc[4][4][4];
#pragma unroll
    for (int i = 0; i < 4; i++)
#pragma unroll
        for (int j = 0; j < 4; j++)
#pragma unroll
            for (int q = 0; q < 4; q++) acc[i][j][q] = 0.f;

    const int nt = 144;   // 9 taps * 16 channel-tiles

    auto stage = [&](int t, int st) {
        const int r  = t >> 4;           // tap 0..8
        const int ct = t & 15;           // channel tile
        const int dy = r / 3 - 1;
        const int c  = ct * 16 + sk;
        uint32_t da = saA + (uint32_t)(st * STAGE_F + sk * AMS + sm8) * 4u;
        int y = ((p0 + sm8) >> 5) + dy;
        bool ok = ((unsigned)y < 32u);
        const float* ga = ok ? (A + (((size_t)bq * C + c) << 10) + p0 + dy * 32 + sm8) : A;
        cp16_pred(da, ga, ok);
        cp16_pred(da + 16, ga + 4, ok);
        uint32_t db = saB + (uint32_t)(st * STAGE_F + sk * AMS + sm8) * 4u;
        const float* gb = Bw + (size_t)(t * BKT + sk) * C + n0 + sm8;
        cp16(db, gb);
        cp16(db + 16, gb + 4);
    };

    stage(0, 0);
    cp_commit();

    const int a5 = lane >> 2;

    for (int t = 0; t < nt; t++) {
        const int cur = t & 1;
        if (t + 1 < nt) {
            stage(t + 1, cur ^ 1);
            cp_commit();
            cp_wait<1>();
        } else {
            cp_wait<0>();
        }
        __syncthreads();

        const int r  = t >> 4;
        const int dx = r % 3 - 1;
        // edge masks: row (m&31)==0 reads x=-1 when dx=-1; (m&31)==31 reads x=32 when dx=+1
        const bool pl = (dx < 0) && (a5 == 0);   // applies to af[.][0],[2] when mi even
        const bool ph = (dx > 0) && (a5 == 7);   // applies to af[.][1],[3] when mi odd

        const float* fA = sA + cur * STAGE_F;
        const float* fB = sB + cur * STAGE_F;
#pragma unroll
        for (int ks = 0; ks < 2; ks++) {
            const int kc = ks * 8 + (lane & 3);
            unsigned af[4][4], bf[4][2];
#pragma unroll
            for (int mi = 0; mi < 4; mi++) {
                int ar = wm * 64 + mi * 16 + a5 + dx;
                bool mlo = pl && ((mi & 1) == 0);
                bool mhi = ph && ((mi & 1) == 1);
                float v0 = fA[kc * AMS + ar];
                float v1 = fA[kc * AMS + ar + 8];
                float v2 = fA[(kc + 4) * AMS + ar];
                float v3 = fA[(kc + 4) * AMS + ar + 8];
                if (mlo) { v0 = 0.f; v2 = 0.f; }
                if (mhi) { v1 = 0.f; v3 = 0.f; }
                af[mi][0] = __float_as_uint(v0);
                af[mi][1] = __float_as_uint(v1);
                af[mi][2] = __float_as_uint(v2);
                af[mi][3] = __float_as_uint(v3);
            }
#pragma unroll
            for (int nj = 0; nj < 4; nj++) {
                int br = wn * 32 + nj * 8 + a5;
                bf[nj][0] = __float_as_uint(fB[kc * AMS + br]);
                bf[nj][1] = __float_as_uint(fB[(kc + 4) * AMS + br]);
            }
#pragma unroll
            for (int mi = 0; mi < 4; mi++)
#pragma unroll
                for (int nj = 0; nj < 4; nj++)
                    mma_tf32(acc[mi][nj], af[mi], bf[nj]);
        }
        __syncthreads();
    }

#pragma unroll
    for (int mi = 0; mi < 4; mi++) {
#pragma unroll
        for (int half = 0; half < 2; half++) {
            int m = m0 + wm * 64 + mi * 16 + a5 + half * 8;
            int mb = m >> 10, p = m & 1023;
#pragma unroll
            for (int nj = 0; nj < 4; nj++) {
                int n = n0 + wn * 32 + nj * 8 + 2 * (lane & 3);
                float v0 = acc[mi][nj][half * 2 + 0] + bias[n];
                float v1 = acc[mi][nj][half * 2 + 1] + bias[n + 1];
                size_t addr = (((size_t)mb * C + n) << 10) + p;
                if (EPI == 1) { v0 = fmaxf(v0, 0.f); v1 = fmaxf(v1, 0.f); }
                if (ROUND) { v0 = to_tf32(v0); v1 = to_tf32(v1); }
                Cout[addr]        = v0;
                Cout[addr + 1024] = v1;
            }
        }
    }
}

// ---------------- attention kernel (TF32 mma, natural d-major staging) ----------
#define SSTR 1044   // 1044 % 32 = 20 -> conflict-free P-frag loads
#define QS2 36      // sQ [d][q], 36 % 32 = 4
#define KS2 132     // sK [d][key], 132 % 32 = 4
#define VSTR 132    // sV [d][key]

__global__ void __launch_bounds__(256, 1) attn_kernel(
    const float* __restrict__ qkv, float* __restrict__ out)
{
    extern __shared__ float sm[];
    float* sS   = sm;                    // [32][SSTR]
    float* sQ   = sS + 32 * SSTR;        // [32 d][QS2]
    float* sK   = sQ + 32 * QS2;         // [32 d][KS2]
    float* sV   = sK + 32 * KS2;         // [32 d][VSTR]
    float* sO   = sV + 32 * VSTR;        // [8][32][33]
    float* sInv = sO + 8 * 32 * 33;      // [32]

    const int tid  = threadIdx.x;
    const int lane = tid & 31;
    const int w    = tid >> 5;
    const int n0 = blockIdx.x * 32;
    const int h  = blockIdx.y;
    const int b  = blockIdx.z;

    const float* qbase = qkv + ((size_t)b * 768 + h * HDIM) * HW;
    const float* kbase = qbase + 256 * HW;
    const float* vbase = qbase + 512 * HW;
    const float scale = 0.17677669529663687f;  // 1/sqrt(32)

    // ---- stage Q [d][q] (one float4 per thread)
    {
        int d = tid >> 3, q4 = (tid & 7) * 4;
        *(float4*)&sQ[d * QS2 + q4] = *(const float4*)&qbase[d * HW + n0 + q4];
    }
    __syncthreads();

    // hoisted Q fragments (A row-major [q][d], read from [d][q] layout)
    unsigned aq[2][4][4];
#pragma unroll
    for (int mi = 0; mi < 2; mi++)
#pragma unroll
        for (int ks = 0; ks < 4; ks++) {
            int qr = mi * 16 + (lane >> 2);
            int dc = ks * 8 + (lane & 3);
            aq[mi][ks][0] = __float_as_uint(sQ[dc * QS2 + qr]);
            aq[mi][ks][1] = __float_as_uint(sQ[dc * QS2 + qr + 8]);
            aq[mi][ks][2] = __float_as_uint(sQ[(dc + 4) * QS2 + qr]);
            aq[mi][ks][3] = __float_as_uint(sQ[(dc + 4) * QS2 + qr + 8]);
        }

    // ---- phase A: S = Q^T K
    for (int kt = 0; kt < 8; kt++) {
        __syncthreads();
        for (int i = tid; i < 1024; i += 256) {
            int d = i >> 5, key4 = (i & 31) * 4;
            *(float4*)&sK[d * KS2 + key4] =
                *(const float4*)&kbase[d * HW + kt * 128 + key4];
        }
        __syncthreads();

        float cS[2][2][4];
#pragma unroll
        for (int mi = 0; mi < 2; mi++)
#pragma unroll
            for (int nj = 0; nj < 2; nj++)
#pragma unroll
                for (int q = 0; q < 4; q++) cS[mi][nj][q] = 0.f;

#pragma unroll
        for (int ks = 0; ks < 4; ks++) {
            int dc = ks * 8 + (lane & 3);
#pragma unroll
            for (int nj = 0; nj < 2; nj++) {
                int ncol = w * 16 + nj * 8 + (lane >> 2);
                unsigned bf[2];
                bf[0] = __float_as_uint(sK[dc * KS2 + ncol]);
                bf[1] = __float_as_uint(sK[(dc + 4) * KS2 + ncol]);
#pragma unroll
                for (int mi = 0; mi < 2; mi++)
                    mma_tf32(cS[mi][nj], aq[mi][ks], bf);
            }
        }
#pragma unroll
        for (int mi = 0; mi < 2; mi++)
#pragma unroll
            for (int nj = 0; nj < 2; nj++) {
                int qr = mi * 16 + (lane >> 2);
                int kc = kt * 128 + w * 16 + nj * 8 + 2 * (lane & 3);
                sS[qr * SSTR + kc]           = cS[mi][nj][0] * scale;
                sS[qr * SSTR + kc + 1]       = cS[mi][nj][1] * scale;
                sS[(qr + 8) * SSTR + kc]     = cS[mi][nj][2] * scale;
                sS[(qr + 8) * SSTR + kc + 1] = cS[mi][nj][3] * scale;
            }
    }
    __syncthreads();

    // ---- phase B: softmax over keys (fast_exp on FMA pipe)
#pragma unroll
    for (int r = 0; r < 4; r++) {
        int q = w * 4 + r;
        float* row = sS + q * SSTR;
        float mx = -1e30f;
        for (int m = lane; m < 1024; m += 32) mx = fmaxf(mx, row[m]);
#pragma unroll
        for (int off = 16; off; off >>= 1)
            mx = fmaxf(mx, __shfl_xor_sync(0xffffffffu, mx, off));
        float s = 0.f;
        for (int m = lane; m < 1024; m += 32) {
            float e = fast_exp(row[m] - mx);
            row[m] = e;
            s += e;
        }
#pragma unroll
        for (int off = 16; off; off >>= 1)
            s += __shfl_xor_sync(0xffffffffu, s, off);
        if (lane == 0) sInv[q] = 1.f / s;
    }

    // ---- phase C: O = P V (warp-split keys, smem reduce)
    float cO[2][4][4];
#pragma unroll
    for (int mi = 0; mi < 2; mi++)
#pragma unroll
        for (int nd = 0; nd < 4; nd++)
#pragma unroll
            for (int q = 0; q < 4; q++) cO[mi][nd][q] = 0.f;

    for (int kt = 0; kt < 8; kt++) {
        __syncthreads();
        for (int i = tid; i < 1024; i += 256) {
            int d = i >> 5, key4 = (i & 31) * 4;
            *(float4*)&sV[d * VSTR + key4] =
                *(const float4*)&vbase[d * HW + kt * 128 + key4];
        }
        __syncthreads();

#pragma unroll
        for (int ks = 0; ks < 2; ks++) {
            int kc = w * 16 + ks * 8 + (lane & 3);
            unsigned af[2][4];
#pragma unroll
            for (int mi = 0; mi < 2; mi++) {
                int qr = mi * 16 + (lane >> 2);
                int col = kt * 128 + kc;
                af[mi][0] = __float_as_uint(sS[qr * SSTR + col]);
                af[mi][1] = __float_as_uint(sS[(qr + 8) * SSTR + col]);
                af[mi][2] = __float_as_uint(sS[qr * SSTR + col + 4]);
                af[mi][3] = __float_as_uint(sS[(qr + 8) * SSTR + col + 4]);
            }
#pragma unroll
            for (int nd = 0; nd < 4; nd++) {
                int dc = nd * 8 + (lane >> 2);
                unsigned bf[2];
                bf[0] = __float_as_uint(sV[dc * VSTR + kc]);
                bf[1] = __float_as_uint(sV[dc * VSTR + kc + 4]);
#pragma unroll
                for (int mi = 0; mi < 2; mi++)
                    mma_tf32(cO[mi][nd], af[mi], bf);
            }
        }
    }

#pragma unroll
    for (int mi = 0; mi < 2; mi++)
#pragma unroll
        for (int nd = 0; nd < 4; nd++) {
            int q = mi * 16 + (lane >> 2);
            int d = nd * 8 + 2 * (lane & 3);
            sO[(w * 32 + q) * 33 + d]           = cO[mi][nd][0];
            sO[(w * 32 + q) * 33 + d + 1]       = cO[mi][nd][1];
            sO[(w * 32 + q + 8) * 33 + d]       = cO[mi][nd][2];
            sO[(w * 32 + q + 8) * 33 + d + 1]   = cO[mi][nd][3];
        }
    __syncthreads();

    for (int i = tid; i < 1024; i += 256) {
        int q = i & 31, d = i >> 5;
        float s = 0.f;
#pragma unroll
        for (int ww = 0; ww < 8; ww++)
            s += sO[(ww * 32 + q) * 33 + d];
        out[((size_t)b * C + h * HDIM + d) * HW + n0 + q] = to_tf32(s * sInv[q]);
    }
}

// ---------------- launch ----------------
extern "C" void kernel_launch(void* const* d_in, const int* in_sizes, int n_in,
                              void* d_out, int out_size)
{
    const float* x       = (const float*)d_in[0];
    const float* conv1_w = (const float*)d_in[1];
    const float* conv1_b = (const float*)d_in[2];
    const float* bn1_g   = (const float*)d_in[3];
    const float* bn1_b   = (const float*)d_in[4];
    const float* bn1_m   = (const float*)d_in[5];
    const float* bn1_v   = (const float*)d_in[6];
    const float* conv2_w = (const float*)d_in[7];
    const float* conv2_b = (const float*)d_in[8];
    const float* bn2_g   = (const float*)d_in[9];
    const float* bn2_b   = (const float*)d_in[10];
    const float* bn2_m   = (const float*)d_in[11];
    const float* bn2_v   = (const float*)d_in[12];
    const float* q_w     = (const float*)d_in[13];
    const float* q_b     = (const float*)d_in[14];
    const float* k_w     = (const float*)d_in[15];
    const float* k_b     = (const float*)d_in[16];
    const float* v_w     = (const float*)d_in[17];
    const float* v_b     = (const float*)d_in[18];
    const float* o_w     = (const float*)d_in[19];
    const float* o_b     = (const float*)d_in[20];
    const float* gate    = (const float*)d_in[21];
    float* out           = (float*)d_out;

    float *p_w1t, *p_w2t, *p_b1, *p_b2, *p_wqkv, *p_bqkv, *p_wot;
    float *p_t1, *p_conv, *p_qkv, *p_attn;
    cudaGetSymbolAddress((void**)&p_w1t,  g_w1t);
    cudaGetSymbolAddress((void**)&p_w2t,  g_w2t);
    cudaGetSymbolAddress((void**)&p_b1,   g_b1);
    cudaGetSymbolAddress((void**)&p_b2,   g_b2);
    cudaGetSymbolAddress((void**)&p_wqkv, g_wqkv);
    cudaGetSymbolAddress((void**)&p_bqkv, g_bqkv);
    cudaGetSymbolAddress((void**)&p_wot,  g_wot);
    cudaGetSymbolAddress((void**)&p_t1,   g_t1);
    cudaGetSymbolAddress((void**)&p_conv, g_conv);
    cudaGetSymbolAddress((void**)&p_qkv,  g_qkv);
    cudaGetSymbolAddress((void**)&p_attn, g_attn);

    // weight transform + BN fold
    prep_kernel<<<1024, 256>>>(conv1_w, conv1_b, bn1_g, bn1_b, bn1_m, bn1_v,
                               conv2_w, conv2_b, bn2_g, bn2_b, bn2_m, bn2_v,
                               q_w, q_b, k_w, k_b, v_w, v_b, o_w);

    // conv1 (3x3) + BN + relu -> t1 (tf32-rounded)
    dim3 gConv(M_TOTAL / BM, C / BN);
    convgemm_k<1, 1><<<gConv, 256>>>(x, p_w1t, p_b1, p_t1);
    // conv2 (3x3) + BN -> conv_out (exact)
    convgemm_k<0, 0><<<gConv, 256>>>(p_t1, p_w2t, p_b2, p_conv);
    // fused qkv (1x1) -> qkv buffer (tf32-rounded)
    dim3 gQKV(M_TOTAL / BM, 768 / BN);
    gemm_k<0, 1><<<gQKV, 256>>>(x, p_wqkv, p_bqkv, p_qkv, C, 768,
                                nullptr, nullptr, nullptr);

    // attention
    const int attn_smem = (32 * SSTR + 32 * QS2 + 32 * KS2 + 32 * VSTR
                           + 8 * 32 * 33 + 32) * (int)sizeof(float);
    cudaFuncSetAttribute(attn_kernel, cudaFuncAttributeMaxDynamicSharedMemorySize,
                         attn_smem);
    dim3 gAttn(HW / 32, HEADS, BATCH);
    attn_kernel<<<gAttn, 256, attn_smem>>>(p_qkv, p_attn);

    // out-proj (1x1) + gate + conv residual + input residual + relu -> out
    dim3 gOut(M_TOTAL / BM, C / BN);
    gemm_k<2, 0><<<gOut, 256>>>(p_attn, p_wot, o_b, out, C, C,
                                p_conv, x, gate);
}

// round 6
// speedup vs baseline: 2.6207x; 1.1978x over previous
#include <cuda_runtime.h>
#include <cuda_bf16.h>
#include <cstdint>
#include <math.h>

// Problem constants
#define BATCH 16
#define C 256
#define HW 1024          // 32x32
#define HEADS 8
#define HDIM 32
#define M_TOTAL (BATCH * HW)   // 16384
#define KCONV (C * 9)          // 2304

// ---------------- scratch (static device globals; no runtime allocation) ---------
__device__ float g_w1t[KCONV * C];    // [r][c][n] bn1-folded conv1 weights (tf32)
__device__ float g_w2t[KCONV * C];
__device__ float g_b1[C];
__device__ float g_b2[C];
__device__ float g_wqkv[C * 768];     // [K=256][N=768] (q|k|v transposed, tf32)
__device__ float g_bqkv[768];
__device__ float g_wot[C * C];        // out_w transposed (tf32)
__device__ float g_t1[BATCH * C * HW];
__device__ float g_conv[BATCH * C * HW];
__device__ float g_qkv[BATCH * 768 * HW];
__device__ float g_attn[BATCH * C * HW];

// ---------------- helpers ----------------
__device__ __forceinline__ float to_tf32(float x) {
    float y;
    asm("cvt.rna.tf32.f32 %0, %1;" : "=f"(y) : "f"(x));
    return y;
}

__device__ __forceinline__ void mma_tf32(float* c, const unsigned* a, const unsigned* b) {
    asm volatile(
        "mma.sync.aligned.m16n8k8.row.col.f32.tf32.tf32.f32 "
        "{%0,%1,%2,%3}, {%4,%5,%6,%7}, {%8,%9}, {%0,%1,%2,%3};\n"
        : "+f"(c[0]), "+f"(c[1]), "+f"(c[2]), "+f"(c[3])
        : "r"(a[0]), "r"(a[1]), "r"(a[2]), "r"(a[3]), "r"(b[0]), "r"(b[1]));
}

__device__ __forceinline__ void cp16(uint32_t s, const void* g) {
    asm volatile("cp.async.cg.shared.global [%0], [%1], 16;" :: "r"(s), "l"(g));
}
// predicated 16B: src-size 0 -> zero-fill 16 bytes
__device__ __forceinline__ void cp16_pred(uint32_t s, const void* g, bool ok) {
    int sz = ok ? 16 : 0;
    asm volatile("cp.async.cg.shared.global [%0], [%1], 16, %2;" :: "r"(s), "l"(g), "r"(sz));
}
__device__ __forceinline__ void cp_commit() { asm volatile("cp.async.commit_group;"); }
template<int N> __device__ __forceinline__ void cp_wait() {
    asm volatile("cp.async.wait_group %0;" :: "n"(N));
}

// fast exp on the FMA pipe. x <= 0 expected.
__device__ __forceinline__ float fast_exp(float x) {
    float t = x * 1.4426950408889634f;
    t = fmaxf(t, -126.0f);
    float fi = floorf(t);
    float f = t - fi;
    float p = fmaf(f, 0.0015041f, 0.0096181f);
    p = fmaf(f, p, 0.0555041f);
    p = fmaf(f, p, 0.2402265f);
    p = fmaf(f, p, 0.6931472f);
    p = fmaf(f, p, 1.0f);
    int e = (int)fi;
    return p * __int_as_float((e + 127) << 23);
}

// ---------------- weight transform + BN fold ----------------
__global__ void prep_kernel(
    const float* __restrict__ conv1_w, const float* __restrict__ conv1_b,
    const float* __restrict__ g1, const float* __restrict__ be1,
    const float* __restrict__ m1, const float* __restrict__ v1,
    const float* __restrict__ conv2_w, const float* __restrict__ conv2_b,
    const float* __restrict__ g2, const float* __restrict__ be2,
    const float* __restrict__ m2, const float* __restrict__ v2,
    const float* __restrict__ q_w, const float* __restrict__ q_b,
    const float* __restrict__ k_w, const float* __restrict__ k_b,
    const float* __restrict__ v_w, const float* __restrict__ v_b,
    const float* __restrict__ o_w)
{
    const int W1T_N = KCONV * C;          // 589824
    const int QKV_N = C * 768;            // 196608
    const int WOT_N = C * C;              // 65536
    const int total = 2 * W1T_N + QKV_N + WOT_N + 768 + 512;
    for (int i = blockIdx.x * blockDim.x + threadIdx.x; i < total;
         i += gridDim.x * blockDim.x) {
        if (i < W1T_N) {
            int k = i >> 8, o = i & 255;       // k = r*256 + c
            int r = k >> 8, c = k & 255;
            float s = g1[o] * rsqrtf(v1[o] + 1e-5f);
            g_w1t[i] = to_tf32(conv1_w[(o * C + c) * 9 + r] * s);
        } else if (i < 2 * W1T_N) {
            int j = i - W1T_N;
            int k = j >> 8, o = j & 255;
            int r = k >> 8, c = k & 255;
            float s = g2[o] * rsqrtf(v2[o] + 1e-5f);
            g_w2t[j] = to_tf32(conv2_w[(o * C + c) * 9 + r] * s);
        } else if (i < 2 * W1T_N + QKV_N) {
            int j = i - 2 * W1T_N;
            int c = j / 768, n = j - c * 768;
            float w;
            if (n < 256)      w = q_w[n * C + c];
            else if (n < 512) w = k_w[(n - 256) * C + c];
            else              w = v_w[(n - 512) * C + c];
            g_wqkv[j] = to_tf32(w);
        } else if (i < 2 * W1T_N + QKV_N + WOT_N) {
            int j = i - (2 * W1T_N + QKV_N);
            int c = j >> 8, o = j & 255;
            g_wot[j] = to_tf32(o_w[o * C + c]);
        } else if (i < 2 * W1T_N + QKV_N + WOT_N + 768) {
            int n = i - (2 * W1T_N + QKV_N + WOT_N);
            float bb;
            if (n < 256)      bb = q_b[n];
            else if (n < 512) bb = k_b[n - 256];
            else              bb = v_b[n - 512];
            g_bqkv[n] = bb;
        } else {
            int j = i - (2 * W1T_N + QKV_N + WOT_N + 768); // 0..511
            int o = j & 255;
            if (j < 256) {
                float s = g1[o] * rsqrtf(v1[o] + 1e-5f);
                g_b1[o] = conv1_b[o] * s + be1[o] - m1[o] * s;
            } else {
                float s = g2[o] * rsqrtf(v2[o] + 1e-5f);
                g_b2[o] = conv2_b[o] * s + be2[o] - m2[o] * s;
            }
        }
    }
}

// ---------------- common tile params ----------------
#define BM 128
#define BN 128
#define BKT 16
#define AMS 136   // 136 % 32 = 8 -> conflict-free fragment LDS
#define STAGE_F (BKT * AMS)   // floats per stage per matrix = 2176
#define GEMM_SMEM ((3 * STAGE_F * 2 + 8) * 4)

// ---------------- 1x1 TF32 GEMM (qkv / out-proj), 3-stage cp.async ----------------
// EPI 0: out = acc + bias
// EPI 2: out = relu(conv + sigmoid(gate)*(acc + bias) + resid)
template<int EPI, int ROUND>
__global__ void __launch_bounds__(256, 2) gemm_k(
    const float* __restrict__ A, const float* __restrict__ Bw,
    const float* __restrict__ bias, float* __restrict__ Cout,
    int Kdim, int Ndim,
    const float* __restrict__ convres, const float* __restrict__ resid,
    const float* __restrict__ gp)
{
    extern __shared__ float dyn[];
    float* sA = dyn;
    float* sB = dyn + 3 * STAGE_F;

    const int tid  = threadIdx.x;
    const int lane = tid & 31;
    const int wid  = tid >> 5;
    const int wm   = wid & 1;
    const int wn   = wid >> 1;
    const int m0 = blockIdx.x * BM;
    const int n0 = blockIdx.y * BN;
    const int bq = m0 >> 10;
    const int p0 = m0 & 1023;

    const int sk  = tid >> 4;
    const int sm8 = (tid & 15) * 8;

    const uint32_t saA = (uint32_t)__cvta_generic_to_shared(sA);
    const uint32_t saB = (uint32_t)__cvta_generic_to_shared(sB);

    float acc[4][4][4];
#pragma unroll
    for (int i = 0; i < 4; i++)
#pragma unroll
        for (int j = 0; j < 4; j++)
#pragma unroll
            for (int q = 0; q < 4; q++) acc[i][j][q] = 0.f;

    const int nt = Kdim / BKT;

    auto stage = [&](int t, int st) {
        const int k = t * BKT + sk;
        uint32_t da = saA + (uint32_t)(st * STAGE_F + sk * AMS + sm8) * 4u;
        const float* ga = A + (((size_t)bq * C + k) << 10) + p0 + sm8;
        cp16(da, ga);
        cp16(da + 16, ga + 4);
        uint32_t db = saB + (uint32_t)(st * STAGE_F + sk * AMS + sm8) * 4u;
        const float* gb = Bw + (size_t)k * Ndim + n0 + sm8;
        cp16(db, gb);
        cp16(db + 16, gb + 4);
    };

    stage(0, 0); cp_commit();
    stage(1, 1); cp_commit();

    for (int t = 0; t < nt; t++) {
        const int cur = t % 3;
        cp_wait<1>();
        __syncthreads();
        if (t + 2 < nt) stage(t + 2, (t + 2) % 3);
        cp_commit();

        const float* fA = sA + cur * STAGE_F;
        const float* fB = sB + cur * STAGE_F;
#pragma unroll
        for (int ks = 0; ks < 2; ks++) {
            const int kc = ks * 8 + (lane & 3);
            unsigned af[4][4], bf[4][2];
#pragma unroll
            for (int mi = 0; mi < 4; mi++) {
                int ar = wm * 64 + mi * 16 + (lane >> 2);
                af[mi][0] = __float_as_uint(fA[kc * AMS + ar]);
                af[mi][1] = __float_as_uint(fA[kc * AMS + ar + 8]);
                af[mi][2] = __float_as_uint(fA[(kc + 4) * AMS + ar]);
                af[mi][3] = __float_as_uint(fA[(kc + 4) * AMS + ar + 8]);
            }
#pragma unroll
            for (int nj = 0; nj < 4; nj++) {
                int br = wn * 32 + nj * 8 + (lane >> 2);
                bf[nj][0] = __float_as_uint(fB[kc * AMS + br]);
                bf[nj][1] = __float_as_uint(fB[(kc + 4) * AMS + br]);
            }
#pragma unroll
            for (int mi = 0; mi < 4; mi++)
#pragma unroll
                for (int nj = 0; nj < 4; nj++)
                    mma_tf32(acc[mi][nj], af[mi], bf[nj]);
        }
    }

    float sg = 0.f;
    if (EPI == 2) sg = 1.f / (1.f + __expf(-gp[0]));
#pragma unroll
    for (int mi = 0; mi < 4; mi++) {
#pragma unroll
        for (int half = 0; half < 2; half++) {
            int m = m0 + wm * 64 + mi * 16 + (lane >> 2) + half * 8;
            int mb = m >> 10, p = m & 1023;
#pragma unroll
            for (int nj = 0; nj < 4; nj++) {
                int n = n0 + wn * 32 + nj * 8 + 2 * (lane & 3);
                float v0 = acc[mi][nj][half * 2 + 0] + bias[n];
                float v1 = acc[mi][nj][half * 2 + 1] + bias[n + 1];
                size_t addr = (((size_t)mb * Ndim + n) << 10) + p;
                if (EPI == 2) {
                    float c0 = convres[addr], c1 = convres[addr + 1024];
                    float r0 = resid[addr],   r1 = resid[addr + 1024];
                    v0 = fmaxf(c0 + sg * v0 + r0, 0.f);
                    v1 = fmaxf(c1 + sg * v1 + r1, 0.f);
                }
                if (ROUND) { v0 = to_tf32(v0); v1 = to_tf32(v1); }
                Cout[addr]        = v0;
                Cout[addr + 1024] = v1;
            }
        }
    }
}

// ---------------- conv3x3 as 9 shifted 1x1 GEMMs (3-stage) ----------------
template<int EPI, int ROUND>
__global__ void __launch_bounds__(256, 2) convgemm_k(
    const float* __restrict__ A, const float* __restrict__ Bw,
    const float* __restrict__ bias, float* __restrict__ Cout)
{
    extern __shared__ float dyn[];
    float* sA = dyn + 4;              // guard for ar-1 reads
    float* sB = dyn + 3 * STAGE_F + 8;

    const int tid  = threadIdx.x;
    const int lane = tid & 31;
    const int wid  = tid >> 5;
    const int wm   = wid & 1;
    const int wn   = wid >> 1;
    const int m0 = blockIdx.x * BM;
    const int n0 = blockIdx.y * BN;
    const int bq = m0 >> 10;
    const int p0 = m0 & 1023;

    const int sk  = tid >> 4;        // channel within 16-tile
    const int sm8 = (tid & 15) * 8;

    const uint32_t saA = (uint32_t)__cvta_generic_to_shared(sA);
    const uint32_t saB = (uint32_t)__cvta_generic_to_shared(sB);

    float acc[4][4][4];
#pragma unroll
    for (int i = 0; i < 4; i++)
#pragma unroll
        for (int j = 0; j < 4; j++)
#pragma unroll
            for (int q = 0; q < 4; q++) acc[i][j][q] = 0.f;

    const int nt = 144;   // 9 taps * 16 channel-tiles

    auto stage = [&](int t, int st) {
        const int r  = t >> 4;           // tap 0..8
        const int ct = t & 15;           // channel tile
        const int dy = r / 3 - 1;
        const int c  = ct * 16 + sk;
        uint32_t da = saA + (uint32_t)(st * STAGE_F + sk * AMS + sm8) * 4u;
        int y = ((p0 + sm8) >> 5) + dy;
        bool ok = ((unsigned)y < 32u);
        const float* ga = ok ? (A + (((size_t)bq * C + c) << 10) + p0 + dy * 32 + sm8) : A;
        cp16_pred(da, ga, ok);
        cp16_pred(da + 16, ga + 4, ok);
        uint32_t db = saB + (uint32_t)(st * STAGE_F + sk * AMS + sm8) * 4u;
        const float* gb = Bw + (size_t)(t * BKT + sk) * C + n0 + sm8;
        cp16(db, gb);
        cp16(db + 16, gb + 4);
    };

    stage(0, 0); cp_commit();
    stage(1, 1); cp_commit();

    const int a5 = lane >> 2;

    for (int t = 0; t < nt; t++) {
        const int cur = t % 3;
        cp_wait<1>();
        __syncthreads();
        if (t + 2 < nt) stage(t + 2, (t + 2) % 3);
        cp_commit();

        const int r  = t >> 4;
        const int dx = r % 3 - 1;
        const bool pl = (dx < 0) && (a5 == 0);
        const bool ph = (dx > 0) && (a5 == 7);

        const float* fA = sA + cur * STAGE_F;
        const float* fB = sB + cur * STAGE_F;
#pragma unroll
        for (int ks = 0; ks < 2; ks++) {
            const int kc = ks * 8 + (lane & 3);
            unsigned af[4][4], bf[4][2];
#pragma unroll
            for (int mi = 0; mi < 4; mi++) {
                int ar = wm * 64 + mi * 16 + a5 + dx;
                bool mlo = pl && ((mi & 1) == 0);
                bool mhi = ph && ((mi & 1) == 1);
                float v0 = fA[kc * AMS + ar];
                float v1 = fA[kc * AMS + ar + 8];
                float v2 = fA[(kc + 4) * AMS + ar];
                float v3 = fA[(kc + 4) * AMS + ar + 8];
                if (mlo) { v0 = 0.f; v2 = 0.f; }
                if (mhi) { v1 = 0.f; v3 = 0.f; }
                af[mi][0] = __float_as_uint(v0);
                af[mi][1] = __float_as_uint(v1);
                af[mi][2] = __float_as_uint(v2);
                af[mi][3] = __float_as_uint(v3);
            }
#pragma unroll
            for (int nj = 0; nj < 4; nj++) {
                int br = wn * 32 + nj * 8 + a5;
                bf[nj][0] = __float_as_uint(fB[kc * AMS + br]);
                bf[nj][1] = __float_as_uint(fB[(kc + 4) * AMS + br]);
            }
#pragma unroll
            for (int mi = 0; mi < 4; mi++)
#pragma unroll
                for (int nj = 0; nj < 4; nj++)
                    mma_tf32(acc[mi][nj], af[mi], bf[nj]);
        }
    }

#pragma unroll
    for (int mi = 0; mi < 4; mi++) {
#pragma unroll
        for (int half = 0; half < 2; half++) {
            int m = m0 + wm * 64 + mi * 16 + a5 + half * 8;
            int mb = m >> 10, p = m & 1023;
#pragma unroll
            for (int nj = 0; nj < 4; nj++) {
                int n = n0 + wn * 32 + nj * 8 + 2 * (lane & 3);
                float v0 = acc[mi][nj][half * 2 + 0] + bias[n];
                float v1 = acc[mi][nj][half * 2 + 1] + bias[n + 1];
                size_t addr = (((size_t)mb * C + n) << 10) + p;
                if (EPI == 1) { v0 = fmaxf(v0, 0.f); v1 = fmaxf(v1, 0.f); }
                if (ROUND) { v0 = to_tf32(v0); v1 = to_tf32(v1); }
                Cout[addr]        = v0;
                Cout[addr + 1024] = v1;
            }
        }
    }
}

// ---------------- attention kernel (TF32 mma, 512 threads / 16 warps) ----------
#define SSTR 1044   // 1044 % 32 = 20 -> conflict-free P-frag loads
#define QS2 36      // sQ [d][q]
#define KS2 132     // sK [d][key]
#define VSTR 132    // sV [d][key]

__global__ void __launch_bounds__(512, 1) attn_kernel(
    const float* __restrict__ qkv, float* __restrict__ out)
{
    extern __shared__ float sm[];
    float* sS   = sm;                    // [32][SSTR]
    float* sQ   = sS + 32 * SSTR;        // [32 d][QS2]
    float* sK   = sQ + 32 * QS2;         // [32 d][KS2]
    float* sV   = sK + 32 * KS2;         // [32 d][VSTR]
    float* sO   = sV + 32 * VSTR;        // [8][32][33]
    float* sInv = sO + 8 * 32 * 33;      // [32]

    const int tid  = threadIdx.x;
    const int lane = tid & 31;
    const int w    = tid >> 5;           // 0..15
    const int n0 = blockIdx.x * 32;
    const int h  = blockIdx.y;
    const int b  = blockIdx.z;

    const float* qbase = qkv + ((size_t)b * 768 + h * HDIM) * HW;
    const float* kbase = qbase + 256 * HW;
    const float* vbase = qbase + 512 * HW;
    const float scale = 0.17677669529663687f;  // 1/sqrt(32)

    // ---- stage Q [d][q]
    if (tid < 256) {
        int d = tid >> 3, q4 = (tid & 7) * 4;
        *(float4*)&sQ[d * QS2 + q4] = *(const float4*)&qbase[d * HW + n0 + q4];
    }
    __syncthreads();

    // hoisted Q fragments (A row-major [q][d], from [d][q] layout)
    unsigned aq[2][4][4];
#pragma unroll
    for (int mi = 0; mi < 2; mi++)
#pragma unroll
        for (int ks = 0; ks < 4; ks++) {
            int qr = mi * 16 + (lane >> 2);
            int dc = ks * 8 + (lane & 3);
            aq[mi][ks][0] = __float_as_uint(sQ[dc * QS2 + qr]);
            aq[mi][ks][1] = __float_as_uint(sQ[dc * QS2 + qr + 8]);
            aq[mi][ks][2] = __float_as_uint(sQ[(dc + 4) * QS2 + qr]);
            aq[mi][ks][3] = __float_as_uint(sQ[(dc + 4) * QS2 + qr + 8]);
        }

    // ---- phase A: S = Q^T K  (16 warps, each 8 key-cols per 128-chunk)
    for (int kt = 0; kt < 8; kt++) {
        __syncthreads();
        for (int i = tid; i < 1024; i += 512) {
            int d = i >> 5, key4 = (i & 31) * 4;
            *(float4*)&sK[d * KS2 + key4] =
                *(const float4*)&kbase[d * HW + kt * 128 + key4];
        }
        __syncthreads();

        float cS[2][4];
#pragma unroll
        for (int mi = 0; mi < 2; mi++)
#pragma unroll
            for (int q = 0; q < 4; q++) cS[mi][q] = 0.f;

#pragma unroll
        for (int ks = 0; ks < 4; ks++) {
            int dc = ks * 8 + (lane & 3);
            int ncol = w * 8 + (lane >> 2);
            unsigned bf[2];
            bf[0] = __float_as_uint(sK[dc * KS2 + ncol]);
            bf[1] = __float_as_uint(sK[(dc + 4) * KS2 + ncol]);
#pragma unroll
            for (int mi = 0; mi < 2; mi++)
                mma_tf32(cS[mi], aq[mi][ks], bf);
        }
#pragma unroll
        for (int mi = 0; mi < 2; mi++) {
            int qr = mi * 16 + (lane >> 2);
            int kc = kt * 128 + w * 8 + 2 * (lane & 3);
            sS[qr * SSTR + kc]           = cS[mi][0] * scale;
            sS[qr * SSTR + kc + 1]       = cS[mi][1] * scale;
            sS[(qr + 8) * SSTR + kc]     = cS[mi][2] * scale;
            sS[(qr + 8) * SSTR + kc + 1] = cS[mi][3] * scale;
        }
    }
    __syncthreads();

    // ---- phase B: softmax (2 rows per warp)
#pragma unroll
    for (int r = 0; r < 2; r++) {
        int q = w * 2 + r;
        float* row = sS + q * SSTR;
        float mx = -1e30f;
        for (int m = lane; m < 1024; m += 32) mx = fmaxf(mx, row[m]);
#pragma unroll
        for (int off = 16; off; off >>= 1)
            mx = fmaxf(mx, __shfl_xor_sync(0xffffffffu, mx, off));
        float s = 0.f;
        for (int m = lane; m < 1024; m += 32) {
            float e = fast_exp(row[m] - mx);
            row[m] = e;
            s += e;
        }
#pragma unroll
        for (int off = 16; off; off >>= 1)
            s += __shfl_xor_sync(0xffffffffu, s, off);
        if (lane == 0) sInv[q] = 1.f / s;
    }

    // ---- phase C: O = P V (16 warps split keys 8-wide, 2-round reduce)
    float cO[2][4][4];
#pragma unroll
    for (int mi = 0; mi < 2; mi++)
#pragma unroll
        for (int nd = 0; nd < 4; nd++)
#pragma unroll
            for (int q = 0; q < 4; q++) cO[mi][nd][q] = 0.f;

    for (int kt = 0; kt < 8; kt++) {
        __syncthreads();
        for (int i = tid; i < 1024; i += 512) {
            int d = i >> 5, key4 = (i & 31) * 4;
            *(float4*)&sV[d * VSTR + key4] =
                *(const float4*)&vbase[d * HW + kt * 128 + key4];
        }
        __syncthreads();

        int kc = w * 8 + (lane & 3);
        int col = kt * 128 + kc;
        unsigned af[2][4];
#pragma unroll
        for (int mi = 0; mi < 2; mi++) {
            int qr = mi * 16 + (lane >> 2);
            af[mi][0] = __float_as_uint(sS[qr * SSTR + col]);
            af[mi][1] = __float_as_uint(sS[(qr + 8) * SSTR + col]);
            af[mi][2] = __float_as_uint(sS[qr * SSTR + col + 4]);
            af[mi][3] = __float_as_uint(sS[(qr + 8) * SSTR + col + 4]);
        }
#pragma unroll
        for (int nd = 0; nd < 4; nd++) {
            int dc = nd * 8 + (lane >> 2);
            unsigned bf[2];
            bf[0] = __float_as_uint(sV[dc * VSTR + kc]);
            bf[1] = __float_as_uint(sV[dc * VSTR + kc + 4]);
#pragma unroll
            for (int mi = 0; mi < 2; mi++)
                mma_tf32(cO[mi][nd], af[mi], bf);
        }
    }

    // round 1: warps 8..15 store partials
    if (w >= 8) {
#pragma unroll
        for (int mi = 0; mi < 2; mi++)
#pragma unroll
            for (int nd = 0; nd < 4; nd++) {
                int q = mi * 16 + (lane >> 2);
                int d = nd * 8 + 2 * (lane & 3);
                int base = ((w - 8) * 32 + q) * 33 + d;
                sO[base]            = cO[mi][nd][0];
                sO[base + 1]        = cO[mi][nd][1];
                sO[base + 8 * 33]   = cO[mi][nd][2];
                sO[base + 8 * 33 + 1] = cO[mi][nd][3];
            }
    }
    __syncthreads();
    // round 2: warps 0..7 add partner partials
    if (w < 8) {
#pragma unroll
        for (int mi = 0; mi < 2; mi++)
#pragma unroll
            for (int nd = 0; nd < 4; nd++) {
                int q = mi * 16 + (lane >> 2);
                int d = nd * 8 + 2 * (lane & 3);
                int base = (w * 32 + q) * 33 + d;
                sO[base]              = cO[mi][nd][0] + sO[base];
                sO[base + 1]          = cO[mi][nd][1] + sO[base + 1];
                sO[base + 8 * 33]     = cO[mi][nd][2] + sO[base + 8 * 33];
                sO[base + 8 * 33 + 1] = cO[mi][nd][3] + sO[base + 8 * 33 + 1];
            }
    }
    __syncthreads();

    for (int i = tid; i < 1024; i += 512) {
        int q = i & 31, d = i >> 5;
        float s = 0.f;
#pragma unroll
        for (int ww = 0; ww < 8; ww++)
            s += sO[(ww * 32 + q) * 33 + d];
        out[((size_t)b * C + h * HDIM + d) * HW + n0 + q] = to_tf32(s * sInv[q]);
    }
}

// ---------------- launch ----------------
extern "C" void kernel_launch(void* const* d_in, const int* in_sizes, int n_in,
                              void* d_out, int out_size)
{
    const float* x       = (const float*)d_in[0];
    const float* conv1_w = (const float*)d_in[1];
    const float* conv1_b = (const float*)d_in[2];
    const float* bn1_g   = (const float*)d_in[3];
    const float* bn1_b   = (const float*)d_in[4];
    const float* bn1_m   = (const float*)d_in[5];
    const float* bn1_v   = (const float*)d_in[6];
    const float* conv2_w = (const float*)d_in[7];
    const float* conv2_b = (const float*)d_in[8];
    const float* bn2_g   = (const float*)d_in[9];
    const float* bn2_b   = (const float*)d_in[10];
    const float* bn2_m   = (const float*)d_in[11];
    const float* bn2_v   = (const float*)d_in[12];
    const float* q_w     = (const float*)d_in[13];
    const float* q_b     = (const float*)d_in[14];
    const float* k_w     = (const float*)d_in[15];
    const float* k_b     = (const float*)d_in[16];
    const float* v_w     = (const float*)d_in[17];
    const float* v_b     = (const float*)d_in[18];
    const float* o_w     = (const float*)d_in[19];
    const float* o_b     = (const float*)d_in[20];
    const float* gate    = (const float*)d_in[21];
    float* out           = (float*)d_out;

    float *p_w1t, *p_w2t, *p_b1, *p_b2, *p_wqkv, *p_bqkv, *p_wot;
    float *p_t1, *p_conv, *p_qkv, *p_attn;
    cudaGetSymbolAddress((void**)&p_w1t,  g_w1t);
    cudaGetSymbolAddress((void**)&p_w2t,  g_w2t);
    cudaGetSymbolAddress((void**)&p_b1,   g_b1);
    cudaGetSymbolAddress((void**)&p_b2,   g_b2);
    cudaGetSymbolAddress((void**)&p_wqkv, g_wqkv);
    cudaGetSymbolAddress((void**)&p_bqkv, g_bqkv);
    cudaGetSymbolAddress((void**)&p_wot,  g_wot);
    cudaGetSymbolAddress((void**)&p_t1,   g_t1);
    cudaGetSymbolAddress((void**)&p_conv, g_conv);
    cudaGetSymbolAddress((void**)&p_qkv,  g_qkv);
    cudaGetSymbolAddress((void**)&p_attn, g_attn);

    static cudaStream_t s_side = nullptr;
    static cudaEvent_t ev_fork = nullptr, ev_join = nullptr;
    static bool attrs_set = false;
    if (s_side == nullptr) {
        cudaStreamCreateWithFlags(&s_side, cudaStreamNonBlocking);
        cudaEventCreateWithFlags(&ev_fork, cudaEventDisableTiming);
        cudaEventCreateWithFlags(&ev_join, cudaEventDisableTiming);
    }
    const int attn_smem = (32 * SSTR + 32 * QS2 + 32 * KS2 + 32 * VSTR
                           + 8 * 32 * 33 + 32) * (int)sizeof(float);
    if (!attrs_set) {
        cudaFuncSetAttribute(gemm_k<0, 1>, cudaFuncAttributeMaxDynamicSharedMemorySize, GEMM_SMEM);
        cudaFuncSetAttribute(gemm_k<2, 0>, cudaFuncAttributeMaxDynamicSharedMemorySize, GEMM_SMEM);
        cudaFuncSetAttribute(convgemm_k<1, 1>, cudaFuncAttributeMaxDynamicSharedMemorySize, GEMM_SMEM);
        cudaFuncSetAttribute(convgemm_k<0, 0>, cudaFuncAttributeMaxDynamicSharedMemorySize, GEMM_SMEM);
        cudaFuncSetAttribute(attn_kernel, cudaFuncAttributeMaxDynamicSharedMemorySize, attn_smem);
        attrs_set = true;
    }

    // weight transform + BN fold (both chains depend on it)
    prep_kernel<<<1024, 256>>>(conv1_w, conv1_b, bn1_g, bn1_b, bn1_m, bn1_v,
                               conv2_w, conv2_b, bn2_g, bn2_b, bn2_m, bn2_v,
                               q_w, q_b, k_w, k_b, v_w, v_b, o_w);

    // fork: conv chain on side stream
    cudaEventRecord(ev_fork, 0);
    cudaStreamWaitEvent(s_side, ev_fork, 0);

    dim3 gConv(M_TOTAL / BM, C / BN);
    convgemm_k<1, 1><<<gConv, 256, GEMM_SMEM, s_side>>>(x, p_w1t, p_b1, p_t1);
    convgemm_k<0, 0><<<gConv, 256, GEMM_SMEM, s_side>>>(p_t1, p_w2t, p_b2, p_conv);
    cudaEventRecord(ev_join, s_side);

    // main stream: qkv -> attention
    dim3 gQKV(M_TOTAL / BM, 768 / BN);
    gemm_k<0, 1><<<gQKV, 256, GEMM_SMEM>>>(x, p_wqkv, p_bqkv, p_qkv, C, 768,
                                           nullptr, nullptr, nullptr);
    dim3 gAttn(HW / 32, HEADS, BATCH);
    attn_kernel<<<gAttn, 512, attn_smem>>>(p_qkv, p_attn);

    // join, then fused epilogue GEMM
    cudaStreamWaitEvent(0, ev_join, 0);
    dim3 gOut(M_TOTAL / BM, C / BN);
    gemm_k<2, 0><<<gOut, 256, GEMM_SMEM>>>(p_attn, p_wot, o_b, out, C, C,
                                           p_conv, x, gate);
}